// round 12
// baseline (speedup 1.0000x reference)
#include <cuda_runtime.h>
#include <cuda_bf16.h>
#include <cuda_fp16.h>
#include <cstdint>
#include <math.h>

// Problem constants
#define M_ROWS 32768
#define EDIM   768
#define NHEAD  12
#define HDIM   64
#define PDIM   256
#define BT     128
#define WSZ    (EDIM * EDIM)

// Scratch (allocation-free rule: __device__ globals)
__device__ __half g_xh[M_ROWS * EDIM];
__device__ __half g_yh[M_ROWS * EDIM];
__device__ __half g_wt[4 * WSZ];
__device__ __nv_bfloat16 g_qhi[M_ROWS * EDIM];
__device__ __nv_bfloat16 g_qlo[M_ROWS * EDIM];
__device__ __nv_bfloat16 g_khi[M_ROWS * EDIM];
__device__ __nv_bfloat16 g_klo[M_ROWS * EDIM];
__device__ __nv_bfloat16 g_vhi[M_ROWS * EDIM];
__device__ __nv_bfloat16 g_vlo[M_ROWS * EDIM];

// ---------------------------------------------------------------------------
// helpers
// ---------------------------------------------------------------------------
__device__ __forceinline__ uint32_t smem_u32(const void* p)
{
    uint32_t a;
    asm("{ .reg .u64 t; cvta.to.shared.u64 t, %1; cvt.u32.u64 %0, t; }"
        : "=r"(a) : "l"(p));
    return a;
}

__device__ __forceinline__ void ldsm_x4(uint32_t* r, uint32_t addr)
{
    asm volatile("ldmatrix.sync.aligned.m8n8.x4.shared.b16 {%0,%1,%2,%3}, [%4];"
        : "=r"(r[0]), "=r"(r[1]), "=r"(r[2]), "=r"(r[3]) : "r"(addr));
}

__device__ __forceinline__ void ldsm_x2(uint32_t* r, uint32_t addr)
{
    asm volatile("ldmatrix.sync.aligned.m8n8.x2.shared.b16 {%0,%1}, [%2];"
        : "=r"(r[0]), "=r"(r[1]) : "r"(addr));
}

__device__ __forceinline__ void ldsm_x2t(uint32_t* r, uint32_t addr)
{
    asm volatile("ldmatrix.sync.aligned.m8n8.x2.trans.shared.b16 {%0,%1}, [%2];"
        : "=r"(r[0]), "=r"(r[1]) : "r"(addr));
}

// bf16 mma (attention)
__device__ __forceinline__ void mma16816(float* c, const uint32_t* a, const uint32_t* b)
{
    asm volatile("mma.sync.aligned.m16n8k16.row.col.f32.bf16.bf16.f32 "
        "{%0,%1,%2,%3},{%4,%5,%6,%7},{%8,%9},{%0,%1,%2,%3};"
        : "+f"(c[0]), "+f"(c[1]), "+f"(c[2]), "+f"(c[3])
        : "r"(a[0]), "r"(a[1]), "r"(a[2]), "r"(a[3]), "r"(b[0]), "r"(b[1]));
}

// fp16 mma (GEMMs)
__device__ __forceinline__ void mma16816h(float* c, const uint32_t* a, const uint32_t* b)
{
    asm volatile("mma.sync.aligned.m16n8k16.row.col.f32.f16.f16.f32 "
        "{%0,%1,%2,%3},{%4,%5,%6,%7},{%8,%9},{%0,%1,%2,%3};"
        : "+f"(c[0]), "+f"(c[1]), "+f"(c[2]), "+f"(c[3])
        : "r"(a[0]), "r"(a[1]), "r"(a[2]), "r"(a[3]), "r"(b[0]), "r"(b[1]));
}

__device__ __forceinline__ void cp16(uint32_t saddr, const void* g)
{
    asm volatile("cp.async.cg.shared.global [%0], [%1], 16;"
        :: "r"(saddr), "l"(g) : "memory");
}
#define CP_COMMIT() asm volatile("cp.async.commit_group;" ::: "memory")
#define CP_WAIT1()  asm volatile("cp.async.wait_group 1;" ::: "memory")
#define CP_WAIT0()  asm volatile("cp.async.wait_group 0;" ::: "memory")

__device__ __forceinline__ uint32_t pack2(float x, float y)
{
    __nv_bfloat16 h0 = __float2bfloat16(x);
    __nv_bfloat16 h1 = __float2bfloat16(y);
    return (uint32_t)__bfloat16_as_ushort(h0) | ((uint32_t)__bfloat16_as_ushort(h1) << 16);
}

// split pair into bf16 hi/lo packed words
__device__ __forceinline__ void split2(float a, float b, uint32_t* hi, uint32_t* lo)
{
    __nv_bfloat16 ha = __float2bfloat16(a);
    __nv_bfloat16 hb = __float2bfloat16(b);
    *hi = (uint32_t)__bfloat16_as_ushort(ha) | ((uint32_t)__bfloat16_as_ushort(hb) << 16);
    *lo = pack2(a - __bfloat162float(ha), b - __bfloat162float(hb));
}

// pack pair into fp16 word
__device__ __forceinline__ uint32_t pack2h(float a, float b)
{
    __half ha = __float2half_rn(a);
    __half hb = __float2half_rn(b);
    return (uint32_t)__half_as_ushort(ha) | ((uint32_t)__half_as_ushort(hb) << 16);
}

// ---------------------------------------------------------------------------
// convert fp32 -> fp16 (same layout)
// ---------------------------------------------------------------------------
__global__ void cvt_f16(const float* __restrict__ in, __half* __restrict__ out)
{
    const int i = blockIdx.x * blockDim.x + threadIdx.x;
    float4 v = ((const float4*)in)[i];
    uint2 o;
    o.x = pack2h(v.x, v.y);
    o.y = pack2h(v.z, v.w);
    ((uint2*)out)[i] = o;
}

// transpose 4 weights at once: W[K][N] -> WT[N][K] fp16 (blockIdx.y selects)
__global__ void whalfT4(const float* __restrict__ W0, const float* __restrict__ W1,
                        const float* __restrict__ W2, const float* __restrict__ W3,
                        __half* __restrict__ Wt)
{
    const int id = blockIdx.x * blockDim.x + threadIdx.x;
    const int w  = blockIdx.y;
    const float* W = (w == 0) ? W0 : (w == 1) ? W1 : (w == 2) ? W2 : W3;
    const int n = id / EDIM;
    const int k = id % EDIM;
    Wt[(size_t)w * WSZ + id] = __float2half_rn(W[k * EDIM + n]);
}

// ---------------------------------------------------------------------------
// fp16 single-product GEMM: C = A @ B^T_layout (+bias).
// CTA tile 256x128, 512 threads (16 warps, 4x4), warp tile 64x32.
// Wt holds B transposed [N][K]. 3-stage cp.async pipeline, one barrier/iter.
// B fragments via ldsm_x4 (pairs of n8).
// mode 0: fp32 C.  mode 1: bf16 split (Chi/Clo).  mode 2: rope + bf16 split.
// ---------------------------------------------------------------------------
#define ASTR   40
#define ATILB  (256 * ASTR * 2)          // 20480: A tile (256 rows)
#define BTILB  (128 * ASTR * 2)          // 10240: B tile (128 rows)
#define STGB   (ATILB + BTILB)           // 30720
#define NSTG   3
#define GEMM_SMEM (NSTG * STGB)          // 92160

__global__ __launch_bounds__(512, 1) void gemm_f16(
    const __half* __restrict__ Ah, const __half* __restrict__ Wt,
    const float* __restrict__ bias, int mode, float* __restrict__ C,
    __nv_bfloat16* __restrict__ Chi, __nv_bfloat16* __restrict__ Clo,
    int M, int N, int K)
{
    extern __shared__ char sm[];

    const int tid  = threadIdx.x;
    const int bm   = blockIdx.y * 256;
    const int bn   = blockIdx.x * 128;
    const int warp = tid >> 5;
    const int lane = tid & 31;
    const int wm   = warp >> 2;       // 0..3 -> 64-row slab
    const int wn   = warp & 3;        // 0..3 -> 32-col slab

    // A loader: 2 threads per row (256 rows), 32B each
    const int ra = tid >> 1;
    const int ca = (tid & 1) * 16;    // halves
    // B loader: 4 threads per row (128 rows), 16B each
    const int rb = tid >> 2;
    const int cb = (tid & 3) * 8;     // halves

    const __half* gA = Ah + (size_t)(bm + ra) * K + ca;
    const __half* gB = Wt + (size_t)(bn + rb) * K + cb;

    const uint32_t sb    = smem_u32(sm);
    const uint32_t stA   = (uint32_t)(ra * 80 + ca * 2);
    const uint32_t stB   = (uint32_t)(ATILB + rb * 80 + cb * 2);

    const int lane15 = lane & 15;
    const uint32_t aoff = (uint32_t)((wm * 64 + lane15) * 80 + (lane >> 4) * 16);
    // B x4 address: row = wn*32 + (lane&7) + ((lane>>4)*8), kbyte = ((lane>>3)&1)*16
    const uint32_t boff = (uint32_t)(ATILB +
        (wn * 32 + (lane & 7) + ((lane >> 4) << 3)) * 80 + ((lane >> 3) & 1) * 16);

    float acc[4][4][4];
    #pragma unroll
    for (int i = 0; i < 4; i++) {
        #pragma unroll
        for (int j = 0; j < 4; j++) {
            #pragma unroll
            for (int e = 0; e < 4; e++) {
                acc[i][j][e] = 0.0f;
            }
        }
    }

    const int NIT = K / 32;   // 24

    // prologue: stages 0 and 1
    #pragma unroll
    for (int p = 0; p < 2; p++) {
        const uint32_t base = sb + (uint32_t)p * STGB;
        const int kt = p * 32;
        cp16(base + stA,      gA + kt);
        cp16(base + stA + 16, gA + kt + 8);
        cp16(base + stB,      gB + kt);
        CP_COMMIT();
    }

    int s = 0;
    for (int it = 0; it < NIT; it++) {
        if (it == NIT - 1) {
            CP_WAIT0();
        } else {
            CP_WAIT1();
        }
        __syncthreads();

        if (it + 2 < NIT) {
            int sp = s + 2;
            if (sp >= NSTG) sp -= NSTG;
            const int kt = (it + 2) * 32;
            const uint32_t base = sb + (uint32_t)sp * STGB;
            cp16(base + stA,      gA + kt);
            cp16(base + stA + 16, gA + kt + 8);
            cp16(base + stB,      gB + kt);
            CP_COMMIT();
        }

        const uint32_t bstg = sb + (uint32_t)s * STGB;

        #pragma unroll
        for (int ks = 0; ks < 2; ks++) {
            const uint32_t kb = (uint32_t)(ks * 32);
            uint32_t ah[4][4];
            uint32_t bf[4][2];
            #pragma unroll
            for (int mf = 0; mf < 4; mf++) {
                ldsm_x4(ah[mf], bstg + aoff + mf * 1280 + kb);
            }
            #pragma unroll
            for (int p = 0; p < 2; p++) {
                uint32_t t4[4];
                ldsm_x4(t4, bstg + boff + p * 1280 + kb);
                bf[2 * p][0]     = t4[0];
                bf[2 * p][1]     = t4[1];
                bf[2 * p + 1][0] = t4[2];
                bf[2 * p + 1][1] = t4[3];
            }
            #pragma unroll
            for (int mf = 0; mf < 4; mf++) {
                #pragma unroll
                for (int nf = 0; nf < 4; nf++) {
                    mma16816h(acc[mf][nf], ah[mf], bf[nf]);
                }
            }
        }

        s++;
        if (s >= NSTG) s -= NSTG;
    }

    const int rbase = bm + wm * 64 + (lane >> 2);
    const int cbase = bn + wn * 32 + (lane & 3) * 2;
    #pragma unroll
    for (int nf = 0; nf < 4; nf++) {
        const int col = cbase + nf * 8;
        float bb0 = 0.0f;
        float bb1 = 0.0f;
        if (bias != 0) {
            bb0 = bias[col];
            bb1 = bias[col + 1];
        }
        // rope frequency for this column pair (mode 2)
        const int hd = col & 63;
        const int pr = hd >> 1;
        const int jf = pr & 15;
        const float invf = __expf(-0.57564627324851142f * (float)jf);

        #pragma unroll
        for (int mf = 0; mf < 4; mf++) {
            const int row = rbase + mf * 16;
            float a0 = acc[mf][nf][0] + bb0;
            float a1 = acc[mf][nf][1] + bb1;
            float a2 = acc[mf][nf][2] + bb0;
            float a3 = acc[mf][nf][3] + bb1;

            if (mode == 2) {
                const int p0 = row & 255;
                const int p8 = (row + 8) & 255;
                const float pos0 = (pr < 16) ? (float)(p0 & 15) : (float)(p0 >> 4);
                const float pos8 = (pr < 16) ? (float)(p8 & 15) : (float)(p8 >> 4);
                float s0, c0, s8, c8;
                sincosf(pos0 * invf, &s0, &c0);
                sincosf(pos8 * invf, &s8, &c8);
                const float r0 = a0 * c0 - a1 * s0;
                const float r1 = a1 * c0 + a0 * s0;
                const float r2 = a2 * c8 - a3 * s8;
                const float r3 = a3 * c8 + a2 * s8;
                a0 = r0; a1 = r1; a2 = r2; a3 = r3;
            }

            if (mode >= 1) {
                uint32_t h0, l0, h1, l1;
                split2(a0, a1, &h0, &l0);
                split2(a2, a3, &h1, &l1);
                *(uint32_t*)(Chi + (size_t)row * N + col)       = h0;
                *(uint32_t*)(Clo + (size_t)row * N + col)       = l0;
                *(uint32_t*)(Chi + (size_t)(row + 8) * N + col) = h1;
                *(uint32_t*)(Clo + (size_t)(row + 8) * N + col) = l1;
            } else {
                float2 v0;
                float2 v1;
                v0.x = a0; v0.y = a1;
                v1.x = a2; v1.y = a3;
                *(float2*)(C + (size_t)row * N + col)       = v0;
                *(float2*)(C + (size_t)(row + 8) * N + col) = v1;
            }
        }
    }
}

// ---------------------------------------------------------------------------
// Tensor-core attention (bf16 hi/lo 3-product, unchanged math).
// Writes y as single fp16 for the output GEMM.
// ---------------------------------------------------------------------------
#define SROWB   144
#define ATILEB  (64 * SROWB)
#define ASTGB   (4 * ATILEB)
#define ATTN_SMEM (2 * ASTGB)

__global__ __launch_bounds__(256, 1) void attn_mma(
    const __nv_bfloat16* __restrict__ qhi, const __nv_bfloat16* __restrict__ qlo,
    const __nv_bfloat16* __restrict__ khi, const __nv_bfloat16* __restrict__ klo,
    const __nv_bfloat16* __restrict__ vhi, const __nv_bfloat16* __restrict__ vlo,
    __half* __restrict__ yh)
{
    extern __shared__ char sm[];

    const int tid   = threadIdx.x;
    const int warp  = tid >> 5;
    const int lane  = tid & 31;
    const int l4    = lane >> 2;
    const int l2    = (lane & 3) * 2;
    const int lane15 = lane & 15;

    const int bt   = blockIdx.x;
    const int h    = blockIdx.y >> 1;
    const int half = blockIdx.y & 1;

    const int qrow0 = bt * 256 + half * 128 + warp * 16;
    const uint32_t sb = smem_u32(sm);

    uint32_t qh[4][4];
    uint32_t ql[4][4];
    {
        const size_t qb = (size_t)(qrow0 + l4) * EDIM + h * 64;
        #pragma unroll
        for (int kf = 0; kf < 4; kf++) {
            const int c = kf * 16 + l2;
            qh[kf][0] = *(const uint32_t*)(qhi + qb + c);
            qh[kf][1] = *(const uint32_t*)(qhi + qb + (size_t)8 * EDIM + c);
            qh[kf][2] = *(const uint32_t*)(qhi + qb + c + 8);
            qh[kf][3] = *(const uint32_t*)(qhi + qb + (size_t)8 * EDIM + c + 8);
            ql[kf][0] = *(const uint32_t*)(qlo + qb + c);
            ql[kf][1] = *(const uint32_t*)(qlo + qb + (size_t)8 * EDIM + c);
            ql[kf][2] = *(const uint32_t*)(qlo + qb + c + 8);
            ql[kf][3] = *(const uint32_t*)(qlo + qb + (size_t)8 * EDIM + c + 8);
        }
    }

    float O[8][4];
    #pragma unroll
    for (int nf = 0; nf < 8; nf++) {
        #pragma unroll
        for (int e = 0; e < 4; e++) {
            O[nf][e] = 0.0f;
        }
    }
    float sum0 = 0.0f;
    float sum1 = 0.0f;

    const int lrow0 = tid >> 3;
    const int lseg0 = tid & 7;
    const int lrow1 = (tid + 256) >> 3;
    const int lseg1 = tid & 7;

    #define ATTN_LOAD(c, s) do {                                                   \
        const int jg0 = bt * 256 + (c) * 64;                                        \
        const uint32_t base = sb + (uint32_t)(s) * ASTGB;                           \
        size_t g0 = (size_t)(jg0 + lrow0) * EDIM + h * 64 + lseg0 * 8;              \
        uint32_t d0 = base + (uint32_t)(lrow0 * SROWB + lseg0 * 16);                \
        cp16(d0 + 0 * ATILEB, khi + g0);                                            \
        cp16(d0 + 1 * ATILEB, klo + g0);                                            \
        cp16(d0 + 2 * ATILEB, vhi + g0);                                            \
        cp16(d0 + 3 * ATILEB, vlo + g0);                                            \
        size_t g1 = (size_t)(jg0 + lrow1) * EDIM + h * 64 + lseg1 * 8;              \
        uint32_t d1 = base + (uint32_t)(lrow1 * SROWB + lseg1 * 16);                \
        cp16(d1 + 0 * ATILEB, khi + g1);                                            \
        cp16(d1 + 1 * ATILEB, klo + g1);                                            \
        cp16(d1 + 2 * ATILEB, vhi + g1);                                            \
        cp16(d1 + 3 * ATILEB, vlo + g1);                                            \
        CP_COMMIT();                                                                \
    } while (0)

    ATTN_LOAD(0, 0);

    const uint32_t bqoff = (uint32_t)((lane15 & 7) * SROWB + ((lane15 >> 3) & 1) * 16);
    const uint32_t bvoff = (uint32_t)(lane15 * SROWB);

    for (int c = 0; c < 4; c++) {
        const int s = c & 1;
        if (c < 3) {
            ATTN_LOAD(c + 1, s ^ 1);
            CP_WAIT1();
        } else {
            CP_WAIT0();
        }
        __syncthreads();

        const uint32_t kb = sb + (uint32_t)s * ASTGB;

        float S[8][4];
        #pragma unroll
        for (int nf = 0; nf < 8; nf++) {
            #pragma unroll
            for (int e = 0; e < 4; e++) {
                S[nf][e] = 0.0f;
            }
        }
        #pragma unroll
        for (int nf = 0; nf < 8; nf++) {
            uint32_t bh[4][2];
            uint32_t bl[4][2];
            #pragma unroll
            for (int kf = 0; kf < 4; kf++) {
                const uint32_t a = kb + (uint32_t)(nf * 8 * SROWB + kf * 32) + bqoff;
                ldsm_x2(bh[kf], a);
                ldsm_x2(bl[kf], a + ATILEB);
            }
            #pragma unroll
            for (int kf = 0; kf < 4; kf++) {
                mma16816(S[nf], qh[kf], bh[kf]);
                mma16816(S[nf], qh[kf], bl[kf]);
                mma16816(S[nf], ql[kf], bh[kf]);
            }
        }

        uint32_t ph[4][4];
        uint32_t pl[4][4];
        #pragma unroll
        for (int nf = 0; nf < 8; nf++) {
            float p0 = __expf(S[nf][0] * 0.125f);
            float p1 = __expf(S[nf][1] * 0.125f);
            float p2 = __expf(S[nf][2] * 0.125f);
            float p3 = __expf(S[nf][3] * 0.125f);
            sum0 += p0 + p1;
            sum1 += p2 + p3;
            const int kf2 = nf >> 1;
            const int o   = (nf & 1) * 2;
            split2(p0, p1, &ph[kf2][o],     &pl[kf2][o]);
            split2(p2, p3, &ph[kf2][o + 1], &pl[kf2][o + 1]);
        }

        #pragma unroll
        for (int nf = 0; nf < 8; nf++) {
            #pragma unroll
            for (int kf = 0; kf < 4; kf++) {
                uint32_t vh2[2];
                uint32_t vl2[2];
                const uint32_t a = kb + 2 * ATILEB +
                                   (uint32_t)(kf * 16 * SROWB + nf * 16) + bvoff;
                ldsm_x2t(vh2, a);
                ldsm_x2t(vl2, a + ATILEB);
                mma16816(O[nf], ph[kf], vh2);
                mma16816(O[nf], ph[kf], vl2);
                mma16816(O[nf], pl[kf], vh2);
            }
        }
        __syncthreads();
    }

    sum0 += __shfl_xor_sync(0xffffffffu, sum0, 1);
    sum0 += __shfl_xor_sync(0xffffffffu, sum0, 2);
    sum1 += __shfl_xor_sync(0xffffffffu, sum1, 1);
    sum1 += __shfl_xor_sync(0xffffffffu, sum1, 2);
    const float inv0 = 1.0f / sum0;
    const float inv1 = 1.0f / sum1;

    const size_t r0 = (size_t)(qrow0 + l4) * EDIM;
    const size_t r1 = r0 + (size_t)8 * EDIM;
    #pragma unroll
    for (int nf = 0; nf < 8; nf++) {
        const int col = h * 64 + nf * 8 + l2;
        *(uint32_t*)(yh + r0 + col) = pack2h(O[nf][0] * inv0, O[nf][1] * inv0);
        *(uint32_t*)(yh + r1 + col) = pack2h(O[nf][2] * inv1, O[nf][3] * inv1);
    }
}

// ---------------------------------------------------------------------------
extern "C" void kernel_launch(void* const* d_in, const int* in_sizes, int n_in,
                              void* d_out, int out_size)
{
    const float* x  = (const float*)d_in[0];
    const float* Wq = (const float*)d_in[1];
    const float* bq = (const float*)d_in[2];
    const float* Wk = (const float*)d_in[3];
    const float* bk = (const float*)d_in[4];
    const float* Wv = (const float*)d_in[5];
    const float* bv = (const float*)d_in[6];
    const float* Wo = (const float*)d_in[7];
    float* out = (float*)d_out;

    __half *xh = 0, *yh = 0, *wt = 0;
    __nv_bfloat16 *qhi = 0, *qlo = 0, *khi = 0, *klo = 0, *vhi = 0, *vlo = 0;
    cudaGetSymbolAddress((void**)&xh,  g_xh);
    cudaGetSymbolAddress((void**)&yh,  g_yh);
    cudaGetSymbolAddress((void**)&wt,  g_wt);
    cudaGetSymbolAddress((void**)&qhi, g_qhi);
    cudaGetSymbolAddress((void**)&qlo, g_qlo);
    cudaGetSymbolAddress((void**)&khi, g_khi);
    cudaGetSymbolAddress((void**)&klo, g_klo);
    cudaGetSymbolAddress((void**)&vhi, g_vhi);
    cudaGetSymbolAddress((void**)&vlo, g_vlo);

    cudaFuncSetAttribute(gemm_f16, cudaFuncAttributeMaxDynamicSharedMemorySize, GEMM_SMEM);
    cudaFuncSetAttribute(attn_mma, cudaFuncAttributeMaxDynamicSharedMemorySize, ATTN_SMEM);

    cvt_f16<<<(M_ROWS * EDIM / 4) / 256, 256>>>(x, xh);
    whalfT4<<<dim3(WSZ / 256, 4), 256>>>(Wq, Wk, Wv, Wo, wt);

    dim3 gg(EDIM / 128, M_ROWS / 256);   // (6, 128)

    // Q: GEMM + bias + rope -> bf16 split
    gemm_f16<<<gg, 512, GEMM_SMEM>>>(xh, wt + 0 * WSZ, bq, 2,
                                     (float*)0, qhi, qlo, M_ROWS, EDIM, EDIM);
    // K: GEMM + bias + rope -> bf16 split
    gemm_f16<<<gg, 512, GEMM_SMEM>>>(xh, wt + 1 * WSZ, bk, 2,
                                     (float*)0, khi, klo, M_ROWS, EDIM, EDIM);
    // V: GEMM + bias -> bf16 split
    gemm_f16<<<gg, 512, GEMM_SMEM>>>(xh, wt + 2 * WSZ, bv, 1,
                                     (float*)0, vhi, vlo, M_ROWS, EDIM, EDIM);

    attn_mma<<<dim3(BT, NHEAD * 2), 256, ATTN_SMEM>>>(qhi, qlo, khi, klo, vhi, vlo, yh);

    // output GEMM -> fp32
    gemm_f16<<<gg, 512, GEMM_SMEM>>>(yh, wt + 3 * WSZ, (const float*)0, 0,
                                     out, (__nv_bfloat16*)0, (__nv_bfloat16*)0, M_ROWS, EDIM, EDIM);
}

// round 13
// speedup vs baseline: 1.2620x; 1.2620x over previous
#include <cuda_runtime.h>
#include <cuda_bf16.h>
#include <cuda_fp16.h>
#include <cstdint>
#include <math.h>

// Problem constants
#define M_ROWS 32768
#define EDIM   768
#define NHEAD  12
#define HDIM   64
#define PDIM   256
#define BT     128
#define WSZ    (EDIM * EDIM)

// Scratch (allocation-free rule: __device__ globals)
__device__ __half g_xh[M_ROWS * EDIM];
__device__ __half g_yh[M_ROWS * EDIM];
__device__ __half g_wt[4 * WSZ];
__device__ __nv_bfloat16 g_qhi[M_ROWS * EDIM];
__device__ __nv_bfloat16 g_qlo[M_ROWS * EDIM];
__device__ __nv_bfloat16 g_khi[M_ROWS * EDIM];
__device__ __nv_bfloat16 g_klo[M_ROWS * EDIM];
__device__ __nv_bfloat16 g_vhi[M_ROWS * EDIM];
__device__ __nv_bfloat16 g_vlo[M_ROWS * EDIM];

// ---------------------------------------------------------------------------
// helpers
// ---------------------------------------------------------------------------
__device__ __forceinline__ uint32_t smem_u32(const void* p)
{
    uint32_t a;
    asm("{ .reg .u64 t; cvta.to.shared.u64 t, %1; cvt.u32.u64 %0, t; }"
        : "=r"(a) : "l"(p));
    return a;
}

__device__ __forceinline__ void ldsm_x4(uint32_t* r, uint32_t addr)
{
    asm volatile("ldmatrix.sync.aligned.m8n8.x4.shared.b16 {%0,%1,%2,%3}, [%4];"
        : "=r"(r[0]), "=r"(r[1]), "=r"(r[2]), "=r"(r[3]) : "r"(addr));
}

__device__ __forceinline__ void ldsm_x2(uint32_t* r, uint32_t addr)
{
    asm volatile("ldmatrix.sync.aligned.m8n8.x2.shared.b16 {%0,%1}, [%2];"
        : "=r"(r[0]), "=r"(r[1]) : "r"(addr));
}

__device__ __forceinline__ void ldsm_x2t(uint32_t* r, uint32_t addr)
{
    asm volatile("ldmatrix.sync.aligned.m8n8.x2.trans.shared.b16 {%0,%1}, [%2];"
        : "=r"(r[0]), "=r"(r[1]) : "r"(addr));
}

// bf16 mma (attention)
__device__ __forceinline__ void mma16816(float* c, const uint32_t* a, const uint32_t* b)
{
    asm volatile("mma.sync.aligned.m16n8k16.row.col.f32.bf16.bf16.f32 "
        "{%0,%1,%2,%3},{%4,%5,%6,%7},{%8,%9},{%0,%1,%2,%3};"
        : "+f"(c[0]), "+f"(c[1]), "+f"(c[2]), "+f"(c[3])
        : "r"(a[0]), "r"(a[1]), "r"(a[2]), "r"(a[3]), "r"(b[0]), "r"(b[1]));
}

// fp16 mma (GEMMs)
__device__ __forceinline__ void mma16816h(float* c, const uint32_t* a, const uint32_t* b)
{
    asm volatile("mma.sync.aligned.m16n8k16.row.col.f32.f16.f16.f32 "
        "{%0,%1,%2,%3},{%4,%5,%6,%7},{%8,%9},{%0,%1,%2,%3};"
        : "+f"(c[0]), "+f"(c[1]), "+f"(c[2]), "+f"(c[3])
        : "r"(a[0]), "r"(a[1]), "r"(a[2]), "r"(a[3]), "r"(b[0]), "r"(b[1]));
}

__device__ __forceinline__ void cp16(uint32_t saddr, const void* g)
{
    asm volatile("cp.async.cg.shared.global [%0], [%1], 16;"
        :: "r"(saddr), "l"(g) : "memory");
}
#define CP_COMMIT() asm volatile("cp.async.commit_group;" ::: "memory")
#define CP_WAIT1()  asm volatile("cp.async.wait_group 1;" ::: "memory")
#define CP_WAIT0()  asm volatile("cp.async.wait_group 0;" ::: "memory")

__device__ __forceinline__ uint32_t pack2(float x, float y)
{
    __nv_bfloat16 h0 = __float2bfloat16(x);
    __nv_bfloat16 h1 = __float2bfloat16(y);
    return (uint32_t)__bfloat16_as_ushort(h0) | ((uint32_t)__bfloat16_as_ushort(h1) << 16);
}

// split pair into bf16 hi/lo packed words
__device__ __forceinline__ void split2(float a, float b, uint32_t* hi, uint32_t* lo)
{
    __nv_bfloat16 ha = __float2bfloat16(a);
    __nv_bfloat16 hb = __float2bfloat16(b);
    *hi = (uint32_t)__bfloat16_as_ushort(ha) | ((uint32_t)__bfloat16_as_ushort(hb) << 16);
    *lo = pack2(a - __bfloat162float(ha), b - __bfloat162float(hb));
}

// pack pair into fp16 word
__device__ __forceinline__ uint32_t pack2h(float a, float b)
{
    __half ha = __float2half_rn(a);
    __half hb = __float2half_rn(b);
    return (uint32_t)__half_as_ushort(ha) | ((uint32_t)__half_as_ushort(hb) << 16);
}

// ---------------------------------------------------------------------------
// convert fp32 -> fp16 (same layout)
// ---------------------------------------------------------------------------
__global__ void cvt_f16(const float* __restrict__ in, __half* __restrict__ out)
{
    const int i = blockIdx.x * blockDim.x + threadIdx.x;
    float4 v = ((const float4*)in)[i];
    uint2 o;
    o.x = pack2h(v.x, v.y);
    o.y = pack2h(v.z, v.w);
    ((uint2*)out)[i] = o;
}

// coalesced transpose of 4 weights: W[K][N] -> WT[N][K] fp16 (blockIdx.z selects)
__global__ void wtransT(const float* __restrict__ W0, const float* __restrict__ W1,
                        const float* __restrict__ W2, const float* __restrict__ W3,
                        __half* __restrict__ Wt)
{
    __shared__ float t[32][33];
    const int w = blockIdx.z;
    const float* W = (w == 0) ? W0 : (w == 1) ? W1 : (w == 2) ? W2 : W3;
    const int n0 = blockIdx.x * 32;
    const int k0 = blockIdx.y * 32;
    const int tx = threadIdx.x;
    const int ty = threadIdx.y;

    #pragma unroll
    for (int i = 0; i < 4; i++) {
        t[ty + 8 * i][tx] = W[(size_t)(k0 + ty + 8 * i) * EDIM + n0 + tx];
    }
    __syncthreads();
    #pragma unroll
    for (int i = 0; i < 4; i++) {
        Wt[(size_t)w * WSZ + (size_t)(n0 + ty + 8 * i) * EDIM + k0 + tx] =
            __float2half_rn(t[tx][ty + 8 * i]);
    }
}

// ---------------------------------------------------------------------------
// fp16 single-product GEMM: C = A @ B^T_layout (+bias).
// CTA 128x128, 256 threads (8 warps 2x4), warp 64x32. K-chunk 64 (12 iters).
// XOR-swizzled smem tiles (128B rows, no padding), 3-stage cp.async pipeline,
// one barrier per iter. B fragments via ldsm_x4 pairs.
// mode 0: fp32 C.  mode 1: bf16 split.  mode 2: rope + bf16 split.
// ---------------------------------------------------------------------------
#define KC     64                        // halves per K-iteration
#define TILB   16384                     // 128 rows x 128 B
#define STGB   (2 * TILB)                // 32768 (A + B)
#define NSTG   3
#define GEMM_SMEM (NSTG * STGB)          // 98304

__global__ __launch_bounds__(256, 2) void gemm_f16(
    const __half* __restrict__ Ah, const __half* __restrict__ Wt,
    const float* __restrict__ bias, int mode, float* __restrict__ C,
    __nv_bfloat16* __restrict__ Chi, __nv_bfloat16* __restrict__ Clo,
    int M, int N, int K)
{
    extern __shared__ char sm[];

    const int tid  = threadIdx.x;
    const int bm   = blockIdx.y * 128;
    const int bn   = blockIdx.x * 128;
    const int warp = tid >> 5;
    const int lane = tid & 31;
    const int wm   = warp >> 2;
    const int wn   = warp & 3;

    // loader: 2 threads per row (128 rows), 64 B each (4 cp16), same for A and B
    const int ra  = tid >> 1;
    const int cab = (tid & 1) * 64;                 // byte col base
    const uint32_t xr = (uint32_t)((ra & 7) << 4);  // row swizzle

    const __half* gA = Ah + (size_t)(bm + ra) * K + (cab >> 1);
    const __half* gB = Wt + (size_t)(bn + ra) * K + (cab >> 1);

    const uint32_t sb = smem_u32(sm);
    uint32_t stA[4];
    #pragma unroll
    for (int i = 0; i < 4; i++) {
        stA[i] = (uint32_t)(ra * 128) + (((uint32_t)(cab + 16 * i)) ^ xr);
    }

    // fragment addressing
    const int lane15 = lane & 15;
    const int arow   = wm * 64 + lane15;
    const uint32_t axor = (uint32_t)((arow & 7) << 4);
    const int brow   = wn * 32 + (lane & 7) + ((lane >> 4) << 3);
    const uint32_t bxor = (uint32_t)((lane & 7) << 4);
    const uint32_t acb  = (uint32_t)((lane >> 4) * 16);       // A col byte base
    const uint32_t bcb  = (uint32_t)(((lane >> 3) & 1) * 16); // B col byte base

    float acc[4][4][4];
    #pragma unroll
    for (int i = 0; i < 4; i++) {
        #pragma unroll
        for (int j = 0; j < 4; j++) {
            #pragma unroll
            for (int e = 0; e < 4; e++) {
                acc[i][j][e] = 0.0f;
            }
        }
    }

    const int NIT = K / KC;   // 12

    // prologue: stages 0 and 1
    #pragma unroll
    for (int p = 0; p < 2; p++) {
        const uint32_t base = sb + (uint32_t)p * STGB;
        const int kt = p * KC;
        #pragma unroll
        for (int i = 0; i < 4; i++) {
            cp16(base + stA[i],        gA + kt + 8 * i);
            cp16(base + TILB + stA[i], gB + kt + 8 * i);
        }
        CP_COMMIT();
    }

    int s = 0;
    for (int it = 0; it < NIT; it++) {
        if (it == NIT - 1) {
            CP_WAIT0();
        } else {
            CP_WAIT1();
        }
        __syncthreads();

        if (it + 2 < NIT) {
            int sp = s + 2;
            if (sp >= NSTG) sp -= NSTG;
            const int kt = (it + 2) * KC;
            const uint32_t base = sb + (uint32_t)sp * STGB;
            #pragma unroll
            for (int i = 0; i < 4; i++) {
                cp16(base + stA[i],        gA + kt + 8 * i);
                cp16(base + TILB + stA[i], gB + kt + 8 * i);
            }
            CP_COMMIT();
        }

        const uint32_t bstg = sb + (uint32_t)s * STGB;

        #pragma unroll
        for (int ks = 0; ks < 4; ks++) {
            const uint32_t kb = (uint32_t)(ks * 32);
            uint32_t ah[4][4];
            uint32_t bf[4][2];
            #pragma unroll
            for (int mf = 0; mf < 4; mf++) {
                const uint32_t addr = bstg + (uint32_t)((arow + mf * 16) * 128) +
                                      ((acb + kb) ^ axor);
                ldsm_x4(ah[mf], addr);
            }
            #pragma unroll
            for (int p = 0; p < 2; p++) {
                uint32_t t4[4];
                const uint32_t addr = bstg + TILB +
                                      (uint32_t)((brow + p * 16) * 128) +
                                      ((bcb + kb) ^ bxor);
                ldsm_x4(t4, addr);
                bf[2 * p][0]     = t4[0];
                bf[2 * p][1]     = t4[1];
                bf[2 * p + 1][0] = t4[2];
                bf[2 * p + 1][1] = t4[3];
            }
            #pragma unroll
            for (int mf = 0; mf < 4; mf++) {
                #pragma unroll
                for (int nf = 0; nf < 4; nf++) {
                    mma16816h(acc[mf][nf], ah[mf], bf[nf]);
                }
            }
        }

        s++;
        if (s >= NSTG) s -= NSTG;
    }

    const int rbase = bm + wm * 64 + (lane >> 2);
    const int cbase = bn + wn * 32 + (lane & 3) * 2;
    #pragma unroll
    for (int nf = 0; nf < 4; nf++) {
        const int col = cbase + nf * 8;
        float bb0 = 0.0f;
        float bb1 = 0.0f;
        if (bias != 0) {
            bb0 = bias[col];
            bb1 = bias[col + 1];
        }
        // rope frequency for this column pair (mode 2)
        const int hd = col & 63;
        const int pr = hd >> 1;
        const int jf = pr & 15;
        const float invf = __expf(-0.57564627324851142f * (float)jf);

        #pragma unroll
        for (int mf = 0; mf < 4; mf++) {
            const int row = rbase + mf * 16;
            float a0 = acc[mf][nf][0] + bb0;
            float a1 = acc[mf][nf][1] + bb1;
            float a2 = acc[mf][nf][2] + bb0;
            float a3 = acc[mf][nf][3] + bb1;

            if (mode == 2) {
                const int p0 = row & 255;
                const int p8 = (row + 8) & 255;
                const float pos0 = (pr < 16) ? (float)(p0 & 15) : (float)(p0 >> 4);
                const float pos8 = (pr < 16) ? (float)(p8 & 15) : (float)(p8 >> 4);
                float s0, c0, s8, c8;
                sincosf(pos0 * invf, &s0, &c0);
                sincosf(pos8 * invf, &s8, &c8);
                const float r0 = a0 * c0 - a1 * s0;
                const float r1 = a1 * c0 + a0 * s0;
                const float r2 = a2 * c8 - a3 * s8;
                const float r3 = a3 * c8 + a2 * s8;
                a0 = r0; a1 = r1; a2 = r2; a3 = r3;
            }

            if (mode >= 1) {
                uint32_t h0, l0, h1, l1;
                split2(a0, a1, &h0, &l0);
                split2(a2, a3, &h1, &l1);
                *(uint32_t*)(Chi + (size_t)row * N + col)       = h0;
                *(uint32_t*)(Clo + (size_t)row * N + col)       = l0;
                *(uint32_t*)(Chi + (size_t)(row + 8) * N + col) = h1;
                *(uint32_t*)(Clo + (size_t)(row + 8) * N + col) = l1;
            } else {
                float2 v0;
                float2 v1;
                v0.x = a0; v0.y = a1;
                v1.x = a2; v1.y = a3;
                *(float2*)(C + (size_t)row * N + col)       = v0;
                *(float2*)(C + (size_t)(row + 8) * N + col) = v1;
            }
        }
    }
}

// ---------------------------------------------------------------------------
// Tensor-core attention (bf16 hi/lo 3-product, unchanged math).
// Writes y as single fp16 for the output GEMM.
// ---------------------------------------------------------------------------
#define SROWB   144
#define ATILEB  (64 * SROWB)
#define ASTGB   (4 * ATILEB)
#define ATTN_SMEM (2 * ASTGB)

__global__ __launch_bounds__(256, 1) void attn_mma(
    const __nv_bfloat16* __restrict__ qhi, const __nv_bfloat16* __restrict__ qlo,
    const __nv_bfloat16* __restrict__ khi, const __nv_bfloat16* __restrict__ klo,
    const __nv_bfloat16* __restrict__ vhi, const __nv_bfloat16* __restrict__ vlo,
    __half* __restrict__ yh)
{
    extern __shared__ char sm[];

    const int tid   = threadIdx.x;
    const int warp  = tid >> 5;
    const int lane  = tid & 31;
    const int l4    = lane >> 2;
    const int l2    = (lane & 3) * 2;
    const int lane15 = lane & 15;

    const int bt   = blockIdx.x;
    const int h    = blockIdx.y >> 1;
    const int half = blockIdx.y & 1;

    const int qrow0 = bt * 256 + half * 128 + warp * 16;
    const uint32_t sb = smem_u32(sm);

    uint32_t qh[4][4];
    uint32_t ql[4][4];
    {
        const size_t qb = (size_t)(qrow0 + l4) * EDIM + h * 64;
        #pragma unroll
        for (int kf = 0; kf < 4; kf++) {
            const int c = kf * 16 + l2;
            qh[kf][0] = *(const uint32_t*)(qhi + qb + c);
            qh[kf][1] = *(const uint32_t*)(qhi + qb + (size_t)8 * EDIM + c);
            qh[kf][2] = *(const uint32_t*)(qhi + qb + c + 8);
            qh[kf][3] = *(const uint32_t*)(qhi + qb + (size_t)8 * EDIM + c + 8);
            ql[kf][0] = *(const uint32_t*)(qlo + qb + c);
            ql[kf][1] = *(const uint32_t*)(qlo + qb + (size_t)8 * EDIM + c);
            ql[kf][2] = *(const uint32_t*)(qlo + qb + c + 8);
            ql[kf][3] = *(const uint32_t*)(qlo + qb + (size_t)8 * EDIM + c + 8);
        }
    }

    float O[8][4];
    #pragma unroll
    for (int nf = 0; nf < 8; nf++) {
        #pragma unroll
        for (int e = 0; e < 4; e++) {
            O[nf][e] = 0.0f;
        }
    }
    float sum0 = 0.0f;
    float sum1 = 0.0f;

    const int lrow0 = tid >> 3;
    const int lseg0 = tid & 7;
    const int lrow1 = (tid + 256) >> 3;
    const int lseg1 = tid & 7;

    #define ATTN_LOAD(c, s) do {                                                   \
        const int jg0 = bt * 256 + (c) * 64;                                        \
        const uint32_t base = sb + (uint32_t)(s) * ASTGB;                           \
        size_t g0 = (size_t)(jg0 + lrow0) * EDIM + h * 64 + lseg0 * 8;              \
        uint32_t d0 = base + (uint32_t)(lrow0 * SROWB + lseg0 * 16);                \
        cp16(d0 + 0 * ATILEB, khi + g0);                                            \
        cp16(d0 + 1 * ATILEB, klo + g0);                                            \
        cp16(d0 + 2 * ATILEB, vhi + g0);                                            \
        cp16(d0 + 3 * ATILEB, vlo + g0);                                            \
        size_t g1 = (size_t)(jg0 + lrow1) * EDIM + h * 64 + lseg1 * 8;              \
        uint32_t d1 = base + (uint32_t)(lrow1 * SROWB + lseg1 * 16);                \
        cp16(d1 + 0 * ATILEB, khi + g1);                                            \
        cp16(d1 + 1 * ATILEB, klo + g1);                                            \
        cp16(d1 + 2 * ATILEB, vhi + g1);                                            \
        cp16(d1 + 3 * ATILEB, vlo + g1);                                            \
        CP_COMMIT();                                                                \
    } while (0)

    ATTN_LOAD(0, 0);

    const uint32_t bqoff = (uint32_t)((lane15 & 7) * SROWB + ((lane15 >> 3) & 1) * 16);
    const uint32_t bvoff = (uint32_t)(lane15 * SROWB);

    for (int c = 0; c < 4; c++) {
        const int s = c & 1;
        if (c < 3) {
            ATTN_LOAD(c + 1, s ^ 1);
            CP_WAIT1();
        } else {
            CP_WAIT0();
        }
        __syncthreads();

        const uint32_t kb = sb + (uint32_t)s * ASTGB;

        float S[8][4];
        #pragma unroll
        for (int nf = 0; nf < 8; nf++) {
            #pragma unroll
            for (int e = 0; e < 4; e++) {
                S[nf][e] = 0.0f;
            }
        }
        #pragma unroll
        for (int nf = 0; nf < 8; nf++) {
            uint32_t bh[4][2];
            uint32_t bl[4][2];
            #pragma unroll
            for (int kf = 0; kf < 4; kf++) {
                const uint32_t a = kb + (uint32_t)(nf * 8 * SROWB + kf * 32) + bqoff;
                ldsm_x2(bh[kf], a);
                ldsm_x2(bl[kf], a + ATILEB);
            }
            #pragma unroll
            for (int kf = 0; kf < 4; kf++) {
                mma16816(S[nf], qh[kf], bh[kf]);
                mma16816(S[nf], qh[kf], bl[kf]);
                mma16816(S[nf], ql[kf], bh[kf]);
            }
        }

        uint32_t ph[4][4];
        uint32_t pl[4][4];
        #pragma unroll
        for (int nf = 0; nf < 8; nf++) {
            float p0 = __expf(S[nf][0] * 0.125f);
            float p1 = __expf(S[nf][1] * 0.125f);
            float p2 = __expf(S[nf][2] * 0.125f);
            float p3 = __expf(S[nf][3] * 0.125f);
            sum0 += p0 + p1;
            sum1 += p2 + p3;
            const int kf2 = nf >> 1;
            const int o   = (nf & 1) * 2;
            split2(p0, p1, &ph[kf2][o],     &pl[kf2][o]);
            split2(p2, p3, &ph[kf2][o + 1], &pl[kf2][o + 1]);
        }

        #pragma unroll
        for (int nf = 0; nf < 8; nf++) {
            #pragma unroll
            for (int kf = 0; kf < 4; kf++) {
                uint32_t vh2[2];
                uint32_t vl2[2];
                const uint32_t a = kb + 2 * ATILEB +
                                   (uint32_t)(kf * 16 * SROWB + nf * 16) + bvoff;
                ldsm_x2t(vh2, a);
                ldsm_x2t(vl2, a + ATILEB);
                mma16816(O[nf], ph[kf], vh2);
                mma16816(O[nf], ph[kf], vl2);
                mma16816(O[nf], pl[kf], vh2);
            }
        }
        __syncthreads();
    }

    sum0 += __shfl_xor_sync(0xffffffffu, sum0, 1);
    sum0 += __shfl_xor_sync(0xffffffffu, sum0, 2);
    sum1 += __shfl_xor_sync(0xffffffffu, sum1, 1);
    sum1 += __shfl_xor_sync(0xffffffffu, sum1, 2);
    const float inv0 = 1.0f / sum0;
    const float inv1 = 1.0f / sum1;

    const size_t r0 = (size_t)(qrow0 + l4) * EDIM;
    const size_t r1 = r0 + (size_t)8 * EDIM;
    #pragma unroll
    for (int nf = 0; nf < 8; nf++) {
        const int col = h * 64 + nf * 8 + l2;
        *(uint32_t*)(yh + r0 + col) = pack2h(O[nf][0] * inv0, O[nf][1] * inv0);
        *(uint32_t*)(yh + r1 + col) = pack2h(O[nf][2] * inv1, O[nf][3] * inv1);
    }
}

// ---------------------------------------------------------------------------
extern "C" void kernel_launch(void* const* d_in, const int* in_sizes, int n_in,
                              void* d_out, int out_size)
{
    const float* x  = (const float*)d_in[0];
    const float* Wq = (const float*)d_in[1];
    const float* bq = (const float*)d_in[2];
    const float* Wk = (const float*)d_in[3];
    const float* bk = (const float*)d_in[4];
    const float* Wv = (const float*)d_in[5];
    const float* bv = (const float*)d_in[6];
    const float* Wo = (const float*)d_in[7];
    float* out = (float*)d_out;

    __half *xh = 0, *yh = 0, *wt = 0;
    __nv_bfloat16 *qhi = 0, *qlo = 0, *khi = 0, *klo = 0, *vhi = 0, *vlo = 0;
    cudaGetSymbolAddress((void**)&xh,  g_xh);
    cudaGetSymbolAddress((void**)&yh,  g_yh);
    cudaGetSymbolAddress((void**)&wt,  g_wt);
    cudaGetSymbolAddress((void**)&qhi, g_qhi);
    cudaGetSymbolAddress((void**)&qlo, g_qlo);
    cudaGetSymbolAddress((void**)&khi, g_khi);
    cudaGetSymbolAddress((void**)&klo, g_klo);
    cudaGetSymbolAddress((void**)&vhi, g_vhi);
    cudaGetSymbolAddress((void**)&vlo, g_vlo);

    cudaFuncSetAttribute(gemm_f16, cudaFuncAttributeMaxDynamicSharedMemorySize, GEMM_SMEM);
    cudaFuncSetAttribute(attn_mma, cudaFuncAttributeMaxDynamicSharedMemorySize, ATTN_SMEM);

    cvt_f16<<<(M_ROWS * EDIM / 4) / 256, 256>>>(x, xh);
    wtransT<<<dim3(EDIM / 32, EDIM / 32, 4), dim3(32, 8)>>>(Wq, Wk, Wv, Wo, wt);

    dim3 gg(EDIM / 128, M_ROWS / 128);   // (6, 256)

    // Q: GEMM + bias + rope -> bf16 split
    gemm_f16<<<gg, 256, GEMM_SMEM>>>(xh, wt + 0 * WSZ, bq, 2,
                                     (float*)0, qhi, qlo, M_ROWS, EDIM, EDIM);
    // K: GEMM + bias + rope -> bf16 split
    gemm_f16<<<gg, 256, GEMM_SMEM>>>(xh, wt + 1 * WSZ, bk, 2,
                                     (float*)0, khi, klo, M_ROWS, EDIM, EDIM);
    // V: GEMM + bias -> bf16 split
    gemm_f16<<<gg, 256, GEMM_SMEM>>>(xh, wt + 2 * WSZ, bv, 1,
                                     (float*)0, vhi, vlo, M_ROWS, EDIM, EDIM);

    attn_mma<<<dim3(BT, NHEAD * 2), 256, ATTN_SMEM>>>(qhi, qlo, khi, klo, vhi, vlo, yh);

    // output GEMM -> fp32
    gemm_f16<<<gg, 256, GEMM_SMEM>>>(yh, wt + 3 * WSZ, (const float*)0, 0,
                                     out, (__nv_bfloat16*)0, (__nv_bfloat16*)0, M_ROWS, EDIM, EDIM);
}

// round 14
// speedup vs baseline: 1.5252x; 1.2085x over previous
#include <cuda_runtime.h>
#include <cuda_bf16.h>
#include <cuda_fp16.h>
#include <cstdint>
#include <math.h>

// Problem constants
#define M_ROWS 32768
#define EDIM   768
#define NHEAD  12
#define HDIM   64
#define PDIM   256
#define BT     128
#define WSZ    (EDIM * EDIM)

// Scratch (allocation-free rule: __device__ globals)
__device__ __half g_xh[M_ROWS * EDIM];
__device__ __half g_yh[M_ROWS * EDIM];
__device__ __half g_wt[4 * WSZ];
__device__ __half g_qf[M_ROWS * EDIM];
__device__ __half g_kf[M_ROWS * EDIM];
__device__ __half g_vf[M_ROWS * EDIM];

// ---------------------------------------------------------------------------
// helpers
// ---------------------------------------------------------------------------
__device__ __forceinline__ uint32_t smem_u32(const void* p)
{
    uint32_t a;
    asm("{ .reg .u64 t; cvta.to.shared.u64 t, %1; cvt.u32.u64 %0, t; }"
        : "=r"(a) : "l"(p));
    return a;
}

__device__ __forceinline__ void ldsm_x4(uint32_t* r, uint32_t addr)
{
    asm volatile("ldmatrix.sync.aligned.m8n8.x4.shared.b16 {%0,%1,%2,%3}, [%4];"
        : "=r"(r[0]), "=r"(r[1]), "=r"(r[2]), "=r"(r[3]) : "r"(addr));
}

__device__ __forceinline__ void ldsm_x2(uint32_t* r, uint32_t addr)
{
    asm volatile("ldmatrix.sync.aligned.m8n8.x2.shared.b16 {%0,%1}, [%2];"
        : "=r"(r[0]), "=r"(r[1]) : "r"(addr));
}

__device__ __forceinline__ void ldsm_x2t(uint32_t* r, uint32_t addr)
{
    asm volatile("ldmatrix.sync.aligned.m8n8.x2.trans.shared.b16 {%0,%1}, [%2];"
        : "=r"(r[0]), "=r"(r[1]) : "r"(addr));
}

// fp16 mma
__device__ __forceinline__ void mma16816h(float* c, const uint32_t* a, const uint32_t* b)
{
    asm volatile("mma.sync.aligned.m16n8k16.row.col.f32.f16.f16.f32 "
        "{%0,%1,%2,%3},{%4,%5,%6,%7},{%8,%9},{%0,%1,%2,%3};"
        : "+f"(c[0]), "+f"(c[1]), "+f"(c[2]), "+f"(c[3])
        : "r"(a[0]), "r"(a[1]), "r"(a[2]), "r"(a[3]), "r"(b[0]), "r"(b[1]));
}

__device__ __forceinline__ void cp16(uint32_t saddr, const void* g)
{
    asm volatile("cp.async.cg.shared.global [%0], [%1], 16;"
        :: "r"(saddr), "l"(g) : "memory");
}
#define CP_COMMIT() asm volatile("cp.async.commit_group;" ::: "memory")
#define CP_WAIT1()  asm volatile("cp.async.wait_group 1;" ::: "memory")
#define CP_WAIT0()  asm volatile("cp.async.wait_group 0;" ::: "memory")

// pack pair into fp16 word
__device__ __forceinline__ uint32_t pack2h(float a, float b)
{
    __half ha = __float2half_rn(a);
    __half hb = __float2half_rn(b);
    return (uint32_t)__half_as_ushort(ha) | ((uint32_t)__half_as_ushort(hb) << 16);
}

// split pair into fp16 hi/lo packed words
__device__ __forceinline__ void split2h(float a, float b, uint32_t* hi, uint32_t* lo)
{
    __half ha = __float2half_rn(a);
    __half hb = __float2half_rn(b);
    *hi = (uint32_t)__half_as_ushort(ha) | ((uint32_t)__half_as_ushort(hb) << 16);
    __half la = __float2half_rn(a - __half2float(ha));
    __half lb = __float2half_rn(b - __half2float(hb));
    *lo = (uint32_t)__half_as_ushort(la) | ((uint32_t)__half_as_ushort(lb) << 16);
}

// ---------------------------------------------------------------------------
// convert fp32 -> fp16 (same layout)
// ---------------------------------------------------------------------------
__global__ void cvt_f16(const float* __restrict__ in, __half* __restrict__ out)
{
    const int i = blockIdx.x * blockDim.x + threadIdx.x;
    float4 v = ((const float4*)in)[i];
    uint2 o;
    o.x = pack2h(v.x, v.y);
    o.y = pack2h(v.z, v.w);
    ((uint2*)out)[i] = o;
}

// coalesced transpose of 4 weights: W[K][N] -> WT[N][K] fp16 (blockIdx.z selects)
__global__ void wtransT(const float* __restrict__ W0, const float* __restrict__ W1,
                        const float* __restrict__ W2, const float* __restrict__ W3,
                        __half* __restrict__ Wt)
{
    __shared__ float t[32][33];
    const int w = blockIdx.z;
    const float* W = (w == 0) ? W0 : (w == 1) ? W1 : (w == 2) ? W2 : W3;
    const int n0 = blockIdx.x * 32;
    const int k0 = blockIdx.y * 32;
    const int tx = threadIdx.x;
    const int ty = threadIdx.y;

    #pragma unroll
    for (int i = 0; i < 4; i++) {
        t[ty + 8 * i][tx] = W[(size_t)(k0 + ty + 8 * i) * EDIM + n0 + tx];
    }
    __syncthreads();
    #pragma unroll
    for (int i = 0; i < 4; i++) {
        Wt[(size_t)w * WSZ + (size_t)(n0 + ty + 8 * i) * EDIM + k0 + tx] =
            __float2half_rn(t[tx][ty + 8 * i]);
    }
}

// ---------------------------------------------------------------------------
// fp16 single-product GEMM: C = A @ B^T_layout (+bias).
// CTA 128x128, 256 threads (8 warps 2x4), warp 64x32. K-chunk 64 (12 iters).
// XOR-swizzled smem tiles, 3-stage cp.async pipeline, one barrier per iter.
// mode 0: fp32 C.  mode 1: fp16 Cf.  mode 2: rope + fp16 Cf.
// ---------------------------------------------------------------------------
#define KC     64
#define TILB   16384
#define STGB   (2 * TILB)
#define NSTG   3
#define GEMM_SMEM (NSTG * STGB)          // 98304

__global__ __launch_bounds__(256, 2) void gemm_f16(
    const __half* __restrict__ Ah, const __half* __restrict__ Wt,
    const float* __restrict__ bias, int mode, float* __restrict__ C,
    __half* __restrict__ Cf,
    int M, int N, int K)
{
    extern __shared__ char sm[];

    const int tid  = threadIdx.x;
    const int bm   = blockIdx.y * 128;
    const int bn   = blockIdx.x * 128;
    const int warp = tid >> 5;
    const int lane = tid & 31;
    const int wm   = warp >> 2;
    const int wn   = warp & 3;

    const int ra  = tid >> 1;
    const int cab = (tid & 1) * 64;
    const uint32_t xr = (uint32_t)((ra & 7) << 4);

    const __half* gA = Ah + (size_t)(bm + ra) * K + (cab >> 1);
    const __half* gB = Wt + (size_t)(bn + ra) * K + (cab >> 1);

    const uint32_t sb = smem_u32(sm);
    uint32_t stA[4];
    #pragma unroll
    for (int i = 0; i < 4; i++) {
        stA[i] = (uint32_t)(ra * 128) + (((uint32_t)(cab + 16 * i)) ^ xr);
    }

    const int lane15 = lane & 15;
    const int arow   = wm * 64 + lane15;
    const uint32_t axor = (uint32_t)((arow & 7) << 4);
    const int brow   = wn * 32 + (lane & 7) + ((lane >> 4) << 3);
    const uint32_t bxor = (uint32_t)((lane & 7) << 4);
    const uint32_t acb  = (uint32_t)((lane >> 4) * 16);
    const uint32_t bcb  = (uint32_t)(((lane >> 3) & 1) * 16);

    float acc[4][4][4];
    #pragma unroll
    for (int i = 0; i < 4; i++) {
        #pragma unroll
        for (int j = 0; j < 4; j++) {
            #pragma unroll
            for (int e = 0; e < 4; e++) {
                acc[i][j][e] = 0.0f;
            }
        }
    }

    const int NIT = K / KC;   // 12

    #pragma unroll
    for (int p = 0; p < 2; p++) {
        const uint32_t base = sb + (uint32_t)p * STGB;
        const int kt = p * KC;
        #pragma unroll
        for (int i = 0; i < 4; i++) {
            cp16(base + stA[i],        gA + kt + 8 * i);
            cp16(base + TILB + stA[i], gB + kt + 8 * i);
        }
        CP_COMMIT();
    }

    int s = 0;
    for (int it = 0; it < NIT; it++) {
        if (it == NIT - 1) {
            CP_WAIT0();
        } else {
            CP_WAIT1();
        }
        __syncthreads();

        if (it + 2 < NIT) {
            int sp = s + 2;
            if (sp >= NSTG) sp -= NSTG;
            const int kt = (it + 2) * KC;
            const uint32_t base = sb + (uint32_t)sp * STGB;
            #pragma unroll
            for (int i = 0; i < 4; i++) {
                cp16(base + stA[i],        gA + kt + 8 * i);
                cp16(base + TILB + stA[i], gB + kt + 8 * i);
            }
            CP_COMMIT();
        }

        const uint32_t bstg = sb + (uint32_t)s * STGB;

        #pragma unroll
        for (int ks = 0; ks < 4; ks++) {
            const uint32_t kb = (uint32_t)(ks * 32);
            uint32_t ah[4][4];
            uint32_t bf[4][2];
            #pragma unroll
            for (int mf = 0; mf < 4; mf++) {
                const uint32_t addr = bstg + (uint32_t)((arow + mf * 16) * 128) +
                                      ((acb + kb) ^ axor);
                ldsm_x4(ah[mf], addr);
            }
            #pragma unroll
            for (int p = 0; p < 2; p++) {
                uint32_t t4[4];
                const uint32_t addr = bstg + TILB +
                                      (uint32_t)((brow + p * 16) * 128) +
                                      ((bcb + kb) ^ bxor);
                ldsm_x4(t4, addr);
                bf[2 * p][0]     = t4[0];
                bf[2 * p][1]     = t4[1];
                bf[2 * p + 1][0] = t4[2];
                bf[2 * p + 1][1] = t4[3];
            }
            #pragma unroll
            for (int mf = 0; mf < 4; mf++) {
                #pragma unroll
                for (int nf = 0; nf < 4; nf++) {
                    mma16816h(acc[mf][nf], ah[mf], bf[nf]);
                }
            }
        }

        s++;
        if (s >= NSTG) s -= NSTG;
    }

    const int rbase = bm + wm * 64 + (lane >> 2);
    const int cbase = bn + wn * 32 + (lane & 3) * 2;
    #pragma unroll
    for (int nf = 0; nf < 4; nf++) {
        const int col = cbase + nf * 8;
        float bb0 = 0.0f;
        float bb1 = 0.0f;
        if (bias != 0) {
            bb0 = bias[col];
            bb1 = bias[col + 1];
        }
        const int hd = col & 63;
        const int pr = hd >> 1;
        const int jf = pr & 15;
        const float invf = __expf(-0.57564627324851142f * (float)jf);

        #pragma unroll
        for (int mf = 0; mf < 4; mf++) {
            const int row = rbase + mf * 16;
            float a0 = acc[mf][nf][0] + bb0;
            float a1 = acc[mf][nf][1] + bb1;
            float a2 = acc[mf][nf][2] + bb0;
            float a3 = acc[mf][nf][3] + bb1;

            if (mode == 2) {
                const int p0 = row & 255;
                const int p8 = (row + 8) & 255;
                const float pos0 = (pr < 16) ? (float)(p0 & 15) : (float)(p0 >> 4);
                const float pos8 = (pr < 16) ? (float)(p8 & 15) : (float)(p8 >> 4);
                float s0, c0, s8, c8;
                sincosf(pos0 * invf, &s0, &c0);
                sincosf(pos8 * invf, &s8, &c8);
                const float r0 = a0 * c0 - a1 * s0;
                const float r1 = a1 * c0 + a0 * s0;
                const float r2 = a2 * c8 - a3 * s8;
                const float r3 = a3 * c8 + a2 * s8;
                a0 = r0; a1 = r1; a2 = r2; a3 = r3;
            }

            if (mode >= 1) {
                *(uint32_t*)(Cf + (size_t)row * N + col)       = pack2h(a0, a1);
                *(uint32_t*)(Cf + (size_t)(row + 8) * N + col) = pack2h(a2, a3);
            } else {
                float2 v0;
                float2 v1;
                v0.x = a0; v0.y = a1;
                v1.x = a2; v1.y = a3;
                *(float2*)(C + (size_t)row * N + col)       = v0;
                *(float2*)(C + (size_t)(row + 8) * N + col) = v1;
            }
        }
    }
}

// ---------------------------------------------------------------------------
// Tensor-core attention, all-fp16 inputs (Q,K,V single fp16; P fp16 hi/lo).
// Block = (bt, h, half): 128 q rows, 8 warps x 16 rows. K/V staged in smem
// (64-row chunks, stride 72 halves), double-buffered cp.async.
// Writes y as single fp16.
// ---------------------------------------------------------------------------
#define SROWB   144
#define ATILEB  (64 * SROWB)             // 9216
#define ASTGB   (2 * ATILEB)             // k, v
#define ATTN_SMEM (2 * ASTGB)            // 36864

__global__ __launch_bounds__(256, 2) void attn_mma(
    const __half* __restrict__ qf, const __half* __restrict__ kf2,
    const __half* __restrict__ vf, __half* __restrict__ yh)
{
    extern __shared__ char sm[];

    const int tid   = threadIdx.x;
    const int warp  = tid >> 5;
    const int lane  = tid & 31;
    const int l4    = lane >> 2;
    const int l2    = (lane & 3) * 2;
    const int lane15 = lane & 15;

    const int bt   = blockIdx.x;
    const int h    = blockIdx.y >> 1;
    const int half = blockIdx.y & 1;

    const int qrow0 = bt * 256 + half * 128 + warp * 16;
    const uint32_t sb = smem_u32(sm);

    uint32_t qh[4][4];
    {
        const size_t qb = (size_t)(qrow0 + l4) * EDIM + h * 64;
        #pragma unroll
        for (int kfi = 0; kfi < 4; kfi++) {
            const int c = kfi * 16 + l2;
            qh[kfi][0] = *(const uint32_t*)(qf + qb + c);
            qh[kfi][1] = *(const uint32_t*)(qf + qb + (size_t)8 * EDIM + c);
            qh[kfi][2] = *(const uint32_t*)(qf + qb + c + 8);
            qh[kfi][3] = *(const uint32_t*)(qf + qb + (size_t)8 * EDIM + c + 8);
        }
    }

    float O[8][4];
    #pragma unroll
    for (int nf = 0; nf < 8; nf++) {
        #pragma unroll
        for (int e = 0; e < 4; e++) {
            O[nf][e] = 0.0f;
        }
    }
    float sum0 = 0.0f;
    float sum1 = 0.0f;

    const int lrow0 = tid >> 3;
    const int lseg0 = tid & 7;
    const int lrow1 = (tid + 256) >> 3;

    #define ATTN_LOAD(c, s) do {                                                   \
        const int jg0 = bt * 256 + (c) * 64;                                        \
        const uint32_t base = sb + (uint32_t)(s) * ASTGB;                           \
        size_t g0 = (size_t)(jg0 + lrow0) * EDIM + h * 64 + lseg0 * 8;              \
        uint32_t d0 = base + (uint32_t)(lrow0 * SROWB + lseg0 * 16);                \
        cp16(d0,          kf2 + g0);                                                \
        cp16(d0 + ATILEB, vf + g0);                                                 \
        size_t g1 = (size_t)(jg0 + lrow1) * EDIM + h * 64 + lseg0 * 8;              \
        uint32_t d1 = base + (uint32_t)(lrow1 * SROWB + lseg0 * 16);                \
        cp16(d1,          kf2 + g1);                                                \
        cp16(d1 + ATILEB, vf + g1);                                                 \
        CP_COMMIT();                                                                \
    } while (0)

    ATTN_LOAD(0, 0);

    const uint32_t bqoff = (uint32_t)((lane15 & 7) * SROWB + ((lane15 >> 3) & 1) * 16);
    const uint32_t bvoff = (uint32_t)(lane15 * SROWB);

    for (int c = 0; c < 4; c++) {
        const int s = c & 1;
        if (c < 3) {
            ATTN_LOAD(c + 1, s ^ 1);
            CP_WAIT1();
        } else {
            CP_WAIT0();
        }
        __syncthreads();

        const uint32_t kb = sb + (uint32_t)s * ASTGB;

        float S[8][4];
        #pragma unroll
        for (int nf = 0; nf < 8; nf++) {
            #pragma unroll
            for (int e = 0; e < 4; e++) {
                S[nf][e] = 0.0f;
            }
        }
        #pragma unroll
        for (int nf = 0; nf < 8; nf++) {
            uint32_t bh[4][2];
            #pragma unroll
            for (int kfi = 0; kfi < 4; kfi++) {
                const uint32_t a = kb + (uint32_t)(nf * 8 * SROWB + kfi * 32) + bqoff;
                ldsm_x2(bh[kfi], a);
            }
            #pragma unroll
            for (int kfi = 0; kfi < 4; kfi++) {
                mma16816h(S[nf], qh[kfi], bh[kfi]);
            }
        }

        uint32_t ph[4][4];
        uint32_t pl[4][4];
        #pragma unroll
        for (int nf = 0; nf < 8; nf++) {
            float p0 = __expf(S[nf][0] * 0.125f);
            float p1 = __expf(S[nf][1] * 0.125f);
            float p2 = __expf(S[nf][2] * 0.125f);
            float p3 = __expf(S[nf][3] * 0.125f);
            sum0 += p0 + p1;
            sum1 += p2 + p3;
            const int kf2i = nf >> 1;
            const int o    = (nf & 1) * 2;
            split2h(p0, p1, &ph[kf2i][o],     &pl[kf2i][o]);
            split2h(p2, p3, &ph[kf2i][o + 1], &pl[kf2i][o + 1]);
        }

        #pragma unroll
        for (int nf = 0; nf < 8; nf++) {
            #pragma unroll
            for (int kfi = 0; kfi < 4; kfi++) {
                uint32_t vh2[2];
                const uint32_t a = kb + ATILEB +
                                   (uint32_t)(kfi * 16 * SROWB + nf * 16) + bvoff;
                ldsm_x2t(vh2, a);
                mma16816h(O[nf], ph[kfi], vh2);
                mma16816h(O[nf], pl[kfi], vh2);
            }
        }
        __syncthreads();
    }

    sum0 += __shfl_xor_sync(0xffffffffu, sum0, 1);
    sum0 += __shfl_xor_sync(0xffffffffu, sum0, 2);
    sum1 += __shfl_xor_sync(0xffffffffu, sum1, 1);
    sum1 += __shfl_xor_sync(0xffffffffu, sum1, 2);
    const float inv0 = 1.0f / sum0;
    const float inv1 = 1.0f / sum1;

    const size_t r0 = (size_t)(qrow0 + l4) * EDIM;
    const size_t r1 = r0 + (size_t)8 * EDIM;
    #pragma unroll
    for (int nf = 0; nf < 8; nf++) {
        const int col = h * 64 + nf * 8 + l2;
        *(uint32_t*)(yh + r0 + col) = pack2h(O[nf][0] * inv0, O[nf][1] * inv0);
        *(uint32_t*)(yh + r1 + col) = pack2h(O[nf][2] * inv1, O[nf][3] * inv1);
    }
}

// ---------------------------------------------------------------------------
extern "C" void kernel_launch(void* const* d_in, const int* in_sizes, int n_in,
                              void* d_out, int out_size)
{
    const float* x  = (const float*)d_in[0];
    const float* Wq = (const float*)d_in[1];
    const float* bq = (const float*)d_in[2];
    const float* Wk = (const float*)d_in[3];
    const float* bk = (const float*)d_in[4];
    const float* Wv = (const float*)d_in[5];
    const float* bv = (const float*)d_in[6];
    const float* Wo = (const float*)d_in[7];
    float* out = (float*)d_out;

    __half *xh = 0, *yh = 0, *wt = 0, *qf = 0, *kf = 0, *vf = 0;
    cudaGetSymbolAddress((void**)&xh, g_xh);
    cudaGetSymbolAddress((void**)&yh, g_yh);
    cudaGetSymbolAddress((void**)&wt, g_wt);
    cudaGetSymbolAddress((void**)&qf, g_qf);
    cudaGetSymbolAddress((void**)&kf, g_kf);
    cudaGetSymbolAddress((void**)&vf, g_vf);

    cudaFuncSetAttribute(gemm_f16, cudaFuncAttributeMaxDynamicSharedMemorySize, GEMM_SMEM);
    cudaFuncSetAttribute(attn_mma, cudaFuncAttributeMaxDynamicSharedMemorySize, ATTN_SMEM);

    cvt_f16<<<(M_ROWS * EDIM / 4) / 256, 256>>>(x, xh);
    wtransT<<<dim3(EDIM / 32, EDIM / 32, 4), dim3(32, 8)>>>(Wq, Wk, Wv, Wo, wt);

    dim3 gg(EDIM / 128, M_ROWS / 128);   // (6, 256)

    // Q: GEMM + bias + rope -> fp16
    gemm_f16<<<gg, 256, GEMM_SMEM>>>(xh, wt + 0 * WSZ, bq, 2,
                                     (float*)0, qf, M_ROWS, EDIM, EDIM);
    // K: GEMM + bias + rope -> fp16
    gemm_f16<<<gg, 256, GEMM_SMEM>>>(xh, wt + 1 * WSZ, bk, 2,
                                     (float*)0, kf, M_ROWS, EDIM, EDIM);
    // V: GEMM + bias -> fp16
    gemm_f16<<<gg, 256, GEMM_SMEM>>>(xh, wt + 2 * WSZ, bv, 1,
                                     (float*)0, vf, M_ROWS, EDIM, EDIM);

    attn_mma<<<dim3(BT, NHEAD * 2), 256, ATTN_SMEM>>>(qf, kf, vf, yh);

    // output GEMM -> fp32
    gemm_f16<<<gg, 256, GEMM_SMEM>>>(yh, wt + 3 * WSZ, (const float*)0, 0,
                                     out, (__half*)0, M_ROWS, EDIM, EDIM);
}

// round 15
// speedup vs baseline: 1.9806x; 1.2986x over previous
#include <cuda_runtime.h>
#include <cuda_fp16.h>
#include <cstdint>
#include <math.h>

// Problem constants
#define M_ROWS 32768
#define EDIM   768
#define NHEAD  12
#define HDIM   64
#define PDIM   256
#define BT     128
#define WSZ    (EDIM * EDIM)
#define NITC   12                        // K chunks of 64 per row strip
#define TILEH  8192                      // halves per 128x128B tile
#define TILB   16384                     // bytes per tile

// Scratch (allocation-free rule: __device__ globals)
// xh, yh, wt are TILED: [blk][chunk][128 rows][128 B, SW128-swizzled]
__device__ __half g_xh[M_ROWS * EDIM];
__device__ __half g_yh[M_ROWS * EDIM];
__device__ __half g_wt[4 * WSZ];
__device__ __half g_qf[M_ROWS * EDIM];
__device__ __half g_kf[M_ROWS * EDIM];
__device__ __half g_vf[M_ROWS * EDIM];

// ---------------------------------------------------------------------------
// helpers
// ---------------------------------------------------------------------------
__device__ __forceinline__ uint32_t smem_u32(const void* p)
{
    uint32_t a;
    asm("{ .reg .u64 t; cvta.to.shared.u64 t, %1; cvt.u32.u64 %0, t; }"
        : "=r"(a) : "l"(p));
    return a;
}

__device__ __forceinline__ void ldsm_x4(uint32_t* r, uint32_t addr)
{
    asm volatile("ldmatrix.sync.aligned.m8n8.x4.shared.b16 {%0,%1,%2,%3}, [%4];"
        : "=r"(r[0]), "=r"(r[1]), "=r"(r[2]), "=r"(r[3]) : "r"(addr));
}

__device__ __forceinline__ void ldsm_x2(uint32_t* r, uint32_t addr)
{
    asm volatile("ldmatrix.sync.aligned.m8n8.x2.shared.b16 {%0,%1}, [%2];"
        : "=r"(r[0]), "=r"(r[1]) : "r"(addr));
}

__device__ __forceinline__ void ldsm_x2t(uint32_t* r, uint32_t addr)
{
    asm volatile("ldmatrix.sync.aligned.m8n8.x2.trans.shared.b16 {%0,%1}, [%2];"
        : "=r"(r[0]), "=r"(r[1]) : "r"(addr));
}

__device__ __forceinline__ void mma16816h(float* c, const uint32_t* a, const uint32_t* b)
{
    asm volatile("mma.sync.aligned.m16n8k16.row.col.f32.f16.f16.f32 "
        "{%0,%1,%2,%3},{%4,%5,%6,%7},{%8,%9},{%0,%1,%2,%3};"
        : "+f"(c[0]), "+f"(c[1]), "+f"(c[2]), "+f"(c[3])
        : "r"(a[0]), "r"(a[1]), "r"(a[2]), "r"(a[3]), "r"(b[0]), "r"(b[1]));
}

__device__ __forceinline__ void cp16(uint32_t saddr, const void* g)
{
    asm volatile("cp.async.cg.shared.global [%0], [%1], 16;"
        :: "r"(saddr), "l"(g) : "memory");
}
#define CP_COMMIT() asm volatile("cp.async.commit_group;" ::: "memory")
#define CP_WAIT1()  asm volatile("cp.async.wait_group 1;" ::: "memory")
#define CP_WAIT0()  asm volatile("cp.async.wait_group 0;" ::: "memory")

// bulk async copy global -> shared with mbarrier completion
__device__ __forceinline__ void bulkcp(uint32_t dst, const void* src,
                                       uint32_t bytes, uint32_t mbar)
{
    asm volatile(
        "cp.async.bulk.shared::cluster.global.mbarrier::complete_tx::bytes "
        "[%0], [%1], %2, [%3];"
        :: "r"(dst), "l"(src), "r"(bytes), "r"(mbar) : "memory");
}

__device__ __forceinline__ void mbar_init(uint32_t a, uint32_t cnt)
{
    asm volatile("mbarrier.init.shared.b64 [%0], %1;" :: "r"(a), "r"(cnt) : "memory");
}

__device__ __forceinline__ void mbar_expect_tx(uint32_t a, uint32_t tx)
{
    asm volatile("mbarrier.arrive.expect_tx.shared.b64 _, [%0], %1;"
        :: "r"(a), "r"(tx) : "memory");
}

__device__ __forceinline__ void mbar_wait(uint32_t a, uint32_t parity)
{
    uint32_t done;
    asm volatile(
        "{\n\t.reg .pred p;\n\t"
        "mbarrier.try_wait.parity.acquire.cta.shared::cta.b64 p, [%1], %2;\n\t"
        "selp.b32 %0, 1, 0, p;\n\t}"
        : "=r"(done) : "r"(a), "r"(parity) : "memory");
    while (!done) {
        asm volatile(
            "{\n\t.reg .pred p;\n\t"
            "mbarrier.try_wait.parity.acquire.cta.shared::cta.b64 p, [%1], %2, 0x989680;\n\t"
            "selp.b32 %0, 1, 0, p;\n\t}"
            : "=r"(done) : "r"(a), "r"(parity) : "memory");
    }
}

__device__ __forceinline__ uint32_t pack2h(float a, float b)
{
    __half ha = __float2half_rn(a);
    __half hb = __float2half_rn(b);
    return (uint32_t)__half_as_ushort(ha) | ((uint32_t)__half_as_ushort(hb) << 16);
}

__device__ __forceinline__ void split2h(float a, float b, uint32_t* hi, uint32_t* lo)
{
    __half ha = __float2half_rn(a);
    __half hb = __float2half_rn(b);
    *hi = (uint32_t)__half_as_ushort(ha) | ((uint32_t)__half_as_ushort(hb) << 16);
    __half la = __float2half_rn(a - __half2float(ha));
    __half lb = __float2half_rn(b - __half2float(hb));
    *lo = (uint32_t)__half_as_ushort(la) | ((uint32_t)__half_as_ushort(lb) << 16);
}

// tiled+swizzled byte offset for element (row m in [0,M), col k in [0,768))
__device__ __forceinline__ size_t tiled_off(int m, int k)
{
    const int r  = m & 127;
    const int cb = (k & 63) * 2;
    const uint32_t sw = (uint32_t)(cb & ~15) ^ (uint32_t)((r & 7) << 4);
    return (size_t)((m >> 7) * NITC + (k >> 6)) * TILB + (size_t)(r * 128)
         + sw + (uint32_t)(cb & 15);
}

// ---------------------------------------------------------------------------
// convert fp32 -> fp16 into TILED layout. One thread = 8 consecutive k.
// ---------------------------------------------------------------------------
__global__ void cvt_f16t(const float* __restrict__ in, __half* __restrict__ out)
{
    const int idx = blockIdx.x * blockDim.x + threadIdx.x;  // over M*96
    const int m  = idx / 96;
    const int kg = idx % 96;
    const int k  = kg * 8;

    const float4 v0 = *(const float4*)(in + (size_t)m * EDIM + k);
    const float4 v1 = *(const float4*)(in + (size_t)m * EDIM + k + 4);
    uint4 o;
    o.x = pack2h(v0.x, v0.y);
    o.y = pack2h(v0.z, v0.w);
    o.z = pack2h(v1.x, v1.y);
    o.w = pack2h(v1.z, v1.w);
    *(uint4*)((char*)out + tiled_off(m, k)) = o;
}

// transpose + pack 4 weights: W[K][N] -> tiled WT (blockIdx.z selects)
__global__ void wtransT(const float* __restrict__ W0, const float* __restrict__ W1,
                        const float* __restrict__ W2, const float* __restrict__ W3,
                        __half* __restrict__ Wt)
{
    __shared__ float t[32][33];
    const int w = blockIdx.z;
    const float* W = (w == 0) ? W0 : (w == 1) ? W1 : (w == 2) ? W2 : W3;
    const int n0 = blockIdx.x * 32;
    const int k0 = blockIdx.y * 32;
    const int tx = threadIdx.x;
    const int ty = threadIdx.y;

    #pragma unroll
    for (int i = 0; i < 4; i++) {
        t[ty + 8 * i][tx] = W[(size_t)(k0 + ty + 8 * i) * EDIM + n0 + tx];
    }
    __syncthreads();
    char* base = (char*)(Wt + (size_t)w * WSZ);
    #pragma unroll
    for (int i = 0; i < 4; i++) {
        const int n = n0 + ty + 8 * i;
        const int k = k0 + tx;
        *(__half*)(base + tiled_off(n, k)) = __float2half_rn(t[tx][ty + 8 * i]);
    }
}

// ---------------------------------------------------------------------------
// fp16 single-product GEMM with BULK staging: C = A @ B^T_layout (+bias).
// A and Wt are TILED gmem ([blk][chunk][16KB swizzled]); one cp.async.bulk
// per tile per chunk, mbarrier completion, 3 stages, one barrier per iter.
// CTA 128x128, 256 threads (8 warps 2x4), warp 64x32. K-chunk 64 (12 iters).
// mode 0: fp32 C.  mode 1: fp16 Cf (linear).  mode 2: rope + fp16 Cf.
// ---------------------------------------------------------------------------
#define STGB   (2 * TILB)
#define NSTG   3
#define GEMM_SMEM (NSTG * STGB)          // 98304

__global__ __launch_bounds__(256, 2) void gemm_f16(
    const __half* __restrict__ Ah, const __half* __restrict__ Wt,
    const float* __restrict__ bias, int mode, float* __restrict__ C,
    __half* __restrict__ Cf,
    int M, int N, int K)
{
    extern __shared__ char sm[];
    __shared__ __align__(8) unsigned long long s_mbar[NSTG];

    const int tid  = threadIdx.x;
    const int bm   = blockIdx.y * 128;
    const int bn   = blockIdx.x * 128;
    const int warp = tid >> 5;
    const int lane = tid & 31;
    const int wm   = warp >> 2;
    const int wn   = warp & 3;

    const uint32_t sb = smem_u32(sm);
    const uint32_t mb0 = smem_u32(&s_mbar[0]);

    const char* gAt = (const char*)(Ah + (size_t)blockIdx.y * NITC * TILEH);
    const char* gBt = (const char*)(Wt + (size_t)blockIdx.x * NITC * TILEH);

    if (tid == 0) {
        mbar_init(mb0 + 0, 1);
        mbar_init(mb0 + 8, 1);
        mbar_init(mb0 + 16, 1);
    }
    __syncthreads();

    if (tid == 0) {
        #pragma unroll
        for (int p = 0; p < 2; p++) {
            const uint32_t mb = mb0 + 8 * p;
            mbar_expect_tx(mb, 2 * TILB);
            const uint32_t base = sb + (uint32_t)p * STGB;
            bulkcp(base,        gAt + (size_t)p * TILB, TILB, mb);
            bulkcp(base + TILB, gBt + (size_t)p * TILB, TILB, mb);
        }
    }

    // fragment addressing
    const int lane15 = lane & 15;
    const int arow   = wm * 64 + lane15;
    const uint32_t axor = (uint32_t)((arow & 7) << 4);
    const int brow   = wn * 32 + (lane & 7) + ((lane >> 4) << 3);
    const uint32_t bxor = (uint32_t)((lane & 7) << 4);
    const uint32_t acb  = (uint32_t)((lane >> 4) * 16);
    const uint32_t bcb  = (uint32_t)(((lane >> 3) & 1) * 16);

    float acc[4][4][4];
    #pragma unroll
    for (int i = 0; i < 4; i++) {
        #pragma unroll
        for (int j = 0; j < 4; j++) {
            #pragma unroll
            for (int e = 0; e < 4; e++) {
                acc[i][j][e] = 0.0f;
            }
        }
    }

    const int NIT = NITC;   // 12

    int s = 0;
    for (int it = 0; it < NIT; it++) {
        __syncthreads();   // WAR: all reads of stage (it+2)%3 (done at it-1) complete

        if (tid == 0 && it + 2 < NIT) {
            int sp = s + 2;
            if (sp >= NSTG) sp -= NSTG;
            const uint32_t mb = mb0 + 8 * sp;
            mbar_expect_tx(mb, 2 * TILB);
            const uint32_t base = sb + (uint32_t)sp * STGB;
            bulkcp(base,        gAt + (size_t)(it + 2) * TILB, TILB, mb);
            bulkcp(base + TILB, gBt + (size_t)(it + 2) * TILB, TILB, mb);
        }

        mbar_wait(mb0 + 8 * s, (uint32_t)((it / 3) & 1));

        const uint32_t bstg = sb + (uint32_t)s * STGB;

        #pragma unroll
        for (int ks = 0; ks < 4; ks++) {
            const uint32_t kb = (uint32_t)(ks * 32);
            uint32_t ah[4][4];
            uint32_t bf[4][2];
            #pragma unroll
            for (int mf = 0; mf < 4; mf++) {
                const uint32_t addr = bstg + (uint32_t)((arow + mf * 16) * 128) +
                                      ((acb + kb) ^ axor);
                ldsm_x4(ah[mf], addr);
            }
            #pragma unroll
            for (int p = 0; p < 2; p++) {
                uint32_t t4[4];
                const uint32_t addr = bstg + TILB +
                                      (uint32_t)((brow + p * 16) * 128) +
                                      ((bcb + kb) ^ bxor);
                ldsm_x4(t4, addr);
                bf[2 * p][0]     = t4[0];
                bf[2 * p][1]     = t4[1];
                bf[2 * p + 1][0] = t4[2];
                bf[2 * p + 1][1] = t4[3];
            }
            #pragma unroll
            for (int mf = 0; mf < 4; mf++) {
                #pragma unroll
                for (int nf = 0; nf < 4; nf++) {
                    mma16816h(acc[mf][nf], ah[mf], bf[nf]);
                }
            }
        }

        s++;
        if (s >= NSTG) s -= NSTG;
    }

    const int rbase = bm + wm * 64 + (lane >> 2);
    const int cbase = bn + wn * 32 + (lane & 3) * 2;
    #pragma unroll
    for (int nf = 0; nf < 4; nf++) {
        const int col = cbase + nf * 8;
        float bb0 = 0.0f;
        float bb1 = 0.0f;
        if (bias != 0) {
            bb0 = bias[col];
            bb1 = bias[col + 1];
        }
        const int hd = col & 63;
        const int pr = hd >> 1;
        const int jf = pr & 15;
        const float invf = __expf(-0.57564627324851142f * (float)jf);

        #pragma unroll
        for (int mf = 0; mf < 4; mf++) {
            const int row = rbase + mf * 16;
            float a0 = acc[mf][nf][0] + bb0;
            float a1 = acc[mf][nf][1] + bb1;
            float a2 = acc[mf][nf][2] + bb0;
            float a3 = acc[mf][nf][3] + bb1;

            if (mode == 2) {
                const int p0 = row & 255;
                const int p8 = (row + 8) & 255;
                const float pos0 = (pr < 16) ? (float)(p0 & 15) : (float)(p0 >> 4);
                const float pos8 = (pr < 16) ? (float)(p8 & 15) : (float)(p8 >> 4);
                float s0, c0, s8, c8;
                sincosf(pos0 * invf, &s0, &c0);
                sincosf(pos8 * invf, &s8, &c8);
                const float r0 = a0 * c0 - a1 * s0;
                const float r1 = a1 * c0 + a0 * s0;
                const float r2 = a2 * c8 - a3 * s8;
                const float r3 = a3 * c8 + a2 * s8;
                a0 = r0; a1 = r1; a2 = r2; a3 = r3;
            }

            if (mode >= 1) {
                *(uint32_t*)(Cf + (size_t)row * N + col)       = pack2h(a0, a1);
                *(uint32_t*)(Cf + (size_t)(row + 8) * N + col) = pack2h(a2, a3);
            } else {
                float2 v0;
                float2 v1;
                v0.x = a0; v0.y = a1;
                v1.x = a2; v1.y = a3;
                *(float2*)(C + (size_t)row * N + col)       = v0;
                *(float2*)(C + (size_t)(row + 8) * N + col) = v1;
            }
        }
    }
}

// ---------------------------------------------------------------------------
// Tensor-core attention, all-fp16 (Q,K,V single fp16; P fp16 hi/lo).
// Writes y as fp16 in TILED layout for the output GEMM.
// ---------------------------------------------------------------------------
#define SROWB   144
#define ATILEB  (64 * SROWB)
#define ASTGB   (2 * ATILEB)
#define ATTN_SMEM (2 * ASTGB)            // 36864

__global__ __launch_bounds__(256, 2) void attn_mma(
    const __half* __restrict__ qf, const __half* __restrict__ kf2,
    const __half* __restrict__ vf, __half* __restrict__ yh)
{
    extern __shared__ char sm[];

    const int tid   = threadIdx.x;
    const int warp  = tid >> 5;
    const int lane  = tid & 31;
    const int l4    = lane >> 2;
    const int l2    = (lane & 3) * 2;
    const int lane15 = lane & 15;

    const int bt   = blockIdx.x;
    const int h    = blockIdx.y >> 1;
    const int half = blockIdx.y & 1;

    const int qrow0 = bt * 256 + half * 128 + warp * 16;
    const uint32_t sb = smem_u32(sm);

    uint32_t qh[4][4];
    {
        const size_t qb = (size_t)(qrow0 + l4) * EDIM + h * 64;
        #pragma unroll
        for (int kfi = 0; kfi < 4; kfi++) {
            const int c = kfi * 16 + l2;
            qh[kfi][0] = *(const uint32_t*)(qf + qb + c);
            qh[kfi][1] = *(const uint32_t*)(qf + qb + (size_t)8 * EDIM + c);
            qh[kfi][2] = *(const uint32_t*)(qf + qb + c + 8);
            qh[kfi][3] = *(const uint32_t*)(qf + qb + (size_t)8 * EDIM + c + 8);
        }
    }

    float O[8][4];
    #pragma unroll
    for (int nf = 0; nf < 8; nf++) {
        #pragma unroll
        for (int e = 0; e < 4; e++) {
            O[nf][e] = 0.0f;
        }
    }
    float sum0 = 0.0f;
    float sum1 = 0.0f;

    const int lrow0 = tid >> 3;
    const int lseg0 = tid & 7;
    const int lrow1 = (tid + 256) >> 3;

    #define ATTN_LOAD(c, s) do {                                                   \
        const int jg0 = bt * 256 + (c) * 64;                                        \
        const uint32_t base = sb + (uint32_t)(s) * ASTGB;                           \
        size_t g0 = (size_t)(jg0 + lrow0) * EDIM + h * 64 + lseg0 * 8;              \
        uint32_t d0 = base + (uint32_t)(lrow0 * SROWB + lseg0 * 16);                \
        cp16(d0,          kf2 + g0);                                                \
        cp16(d0 + ATILEB, vf + g0);                                                 \
        size_t g1 = (size_t)(jg0 + lrow1) * EDIM + h * 64 + lseg0 * 8;              \
        uint32_t d1 = base + (uint32_t)(lrow1 * SROWB + lseg0 * 16);                \
        cp16(d1,          kf2 + g1);                                                \
        cp16(d1 + ATILEB, vf + g1);                                                 \
        CP_COMMIT();                                                                \
    } while (0)

    ATTN_LOAD(0, 0);

    const uint32_t bqoff = (uint32_t)((lane15 & 7) * SROWB + ((lane15 >> 3) & 1) * 16);
    const uint32_t bvoff = (uint32_t)(lane15 * SROWB);

    for (int c = 0; c < 4; c++) {
        const int s = c & 1;
        if (c < 3) {
            ATTN_LOAD(c + 1, s ^ 1);
            CP_WAIT1();
        } else {
            CP_WAIT0();
        }
        __syncthreads();

        const uint32_t kb = sb + (uint32_t)s * ASTGB;

        float S[8][4];
        #pragma unroll
        for (int nf = 0; nf < 8; nf++) {
            #pragma unroll
            for (int e = 0; e < 4; e++) {
                S[nf][e] = 0.0f;
            }
        }
        #pragma unroll
        for (int nf = 0; nf < 8; nf++) {
            uint32_t bh[4][2];
            #pragma unroll
            for (int kfi = 0; kfi < 4; kfi++) {
                const uint32_t a = kb + (uint32_t)(nf * 8 * SROWB + kfi * 32) + bqoff;
                ldsm_x2(bh[kfi], a);
            }
            #pragma unroll
            for (int kfi = 0; kfi < 4; kfi++) {
                mma16816h(S[nf], qh[kfi], bh[kfi]);
            }
        }

        uint32_t ph[4][4];
        uint32_t pl[4][4];
        #pragma unroll
        for (int nf = 0; nf < 8; nf++) {
            float p0 = __expf(S[nf][0] * 0.125f);
            float p1 = __expf(S[nf][1] * 0.125f);
            float p2 = __expf(S[nf][2] * 0.125f);
            float p3 = __expf(S[nf][3] * 0.125f);
            sum0 += p0 + p1;
            sum1 += p2 + p3;
            const int kf2i = nf >> 1;
            const int o    = (nf & 1) * 2;
            split2h(p0, p1, &ph[kf2i][o],     &pl[kf2i][o]);
            split2h(p2, p3, &ph[kf2i][o + 1], &pl[kf2i][o + 1]);
        }

        #pragma unroll
        for (int nf = 0; nf < 8; nf++) {
            #pragma unroll
            for (int kfi = 0; kfi < 4; kfi++) {
                uint32_t vh2[2];
                const uint32_t a = kb + ATILEB +
                                   (uint32_t)(kfi * 16 * SROWB + nf * 16) + bvoff;
                ldsm_x2t(vh2, a);
                mma16816h(O[nf], ph[kfi], vh2);
                mma16816h(O[nf], pl[kfi], vh2);
            }
        }
        __syncthreads();
    }

    sum0 += __shfl_xor_sync(0xffffffffu, sum0, 1);
    sum0 += __shfl_xor_sync(0xffffffffu, sum0, 2);
    sum1 += __shfl_xor_sync(0xffffffffu, sum1, 1);
    sum1 += __shfl_xor_sync(0xffffffffu, sum1, 2);
    const float inv0 = 1.0f / sum0;
    const float inv1 = 1.0f / sum1;

    // write y in TILED layout: kc == h, 4-byte stores within 16B groups
    const int r0g = qrow0 + l4;
    const int r1g = r0g + 8;
    char* yb = (char*)yh;
    #pragma unroll
    for (int nf = 0; nf < 8; nf++) {
        const uint32_t grp = (uint32_t)(nf * 16) ^ (uint32_t)((l4 & 7) << 4);
        const uint32_t within = (uint32_t)((lane & 3) * 4);
        const size_t o0 = (size_t)((r0g >> 7) * NITC + h) * TILB +
                          (size_t)((r0g & 127) * 128) + grp + within;
        const size_t o1 = (size_t)((r1g >> 7) * NITC + h) * TILB +
                          (size_t)((r1g & 127) * 128) + grp + within;
        *(uint32_t*)(yb + o0) = pack2h(O[nf][0] * inv0, O[nf][1] * inv0);
        *(uint32_t*)(yb + o1) = pack2h(O[nf][2] * inv1, O[nf][3] * inv1);
    }
}

// ---------------------------------------------------------------------------
extern "C" void kernel_launch(void* const* d_in, const int* in_sizes, int n_in,
                              void* d_out, int out_size)
{
    const float* x  = (const float*)d_in[0];
    const float* Wq = (const float*)d_in[1];
    const float* bq = (const float*)d_in[2];
    const float* Wk = (const float*)d_in[3];
    const float* bk = (const float*)d_in[4];
    const float* Wv = (const float*)d_in[5];
    const float* bv = (const float*)d_in[6];
    const float* Wo = (const float*)d_in[7];
    float* out = (float*)d_out;

    __half *xh = 0, *yh = 0, *wt = 0, *qf = 0, *kf = 0, *vf = 0;
    cudaGetSymbolAddress((void**)&xh, g_xh);
    cudaGetSymbolAddress((void**)&yh, g_yh);
    cudaGetSymbolAddress((void**)&wt, g_wt);
    cudaGetSymbolAddress((void**)&qf, g_qf);
    cudaGetSymbolAddress((void**)&kf, g_kf);
    cudaGetSymbolAddress((void**)&vf, g_vf);

    cudaFuncSetAttribute(gemm_f16, cudaFuncAttributeMaxDynamicSharedMemorySize, GEMM_SMEM);
    cudaFuncSetAttribute(attn_mma, cudaFuncAttributeMaxDynamicSharedMemorySize, ATTN_SMEM);

    cvt_f16t<<<(M_ROWS * 96) / 256, 256>>>(x, xh);
    wtransT<<<dim3(EDIM / 32, EDIM / 32, 4), dim3(32, 8)>>>(Wq, Wk, Wv, Wo, wt);

    dim3 gg(EDIM / 128, M_ROWS / 128);   // (6, 256)

    // Q: GEMM + bias + rope -> fp16 (linear)
    gemm_f16<<<gg, 256, GEMM_SMEM>>>(xh, wt + 0 * WSZ, bq, 2,
                                     (float*)0, qf, M_ROWS, EDIM, EDIM);
    // K: GEMM + bias + rope -> fp16 (linear)
    gemm_f16<<<gg, 256, GEMM_SMEM>>>(xh, wt + 1 * WSZ, bk, 2,
                                     (float*)0, kf, M_ROWS, EDIM, EDIM);
    // V: GEMM + bias -> fp16 (linear)
    gemm_f16<<<gg, 256, GEMM_SMEM>>>(xh, wt + 2 * WSZ, bv, 1,
                                     (float*)0, vf, M_ROWS, EDIM, EDIM);

    attn_mma<<<dim3(BT, NHEAD * 2), 256, ATTN_SMEM>>>(qf, kf, vf, yh);

    // output GEMM (A = tiled yh) -> fp32
    gemm_f16<<<gg, 256, GEMM_SMEM>>>(yh, wt + 3 * WSZ, (const float*)0, 0,
                                     out, (__half*)0, M_ROWS, EDIM, EDIM);
}

// round 17
// speedup vs baseline: 2.0391x; 1.0295x over previous
#include <cuda_runtime.h>
#include <cuda_fp16.h>
#include <cstdint>
#include <math.h>

// Problem constants
#define M_ROWS 32768
#define EDIM   768
#define NHEAD  12
#define HDIM   64
#define PDIM   256
#define WSZ    (EDIM * EDIM)
#define NITC   12                        // K chunks of 64 per row strip
#define TILEH  8192                      // halves per 128x128B tile
#define TILB   16384                     // bytes per tile
#define PGRID  296                       // persistent grid (2 CTAs/SM floor)

// Scratch (allocation-free rule: __device__ globals)
// xh, yh, wt are TILED: [blk][chunk][128 rows][128 B, SW128-swizzled]
__device__ __half g_xh[M_ROWS * EDIM];
__device__ __half g_yh[M_ROWS * EDIM];
__device__ __half g_wt[4 * WSZ];
__device__ __half g_qf[M_ROWS * EDIM];
__device__ __half g_kf[M_ROWS * EDIM];
__device__ __half g_vf[M_ROWS * EDIM];

// ---------------------------------------------------------------------------
// helpers
// ---------------------------------------------------------------------------
__device__ __forceinline__ uint32_t smem_u32(const void* p)
{
    uint32_t a;
    asm("{ .reg .u64 t; cvta.to.shared.u64 t, %1; cvt.u32.u64 %0, t; }"
        : "=r"(a) : "l"(p));
    return a;
}

__device__ __forceinline__ void ldsm_x4(uint32_t* r, uint32_t addr)
{
    asm volatile("ldmatrix.sync.aligned.m8n8.x4.shared.b16 {%0,%1,%2,%3}, [%4];"
        : "=r"(r[0]), "=r"(r[1]), "=r"(r[2]), "=r"(r[3]) : "r"(addr));
}

__device__ __forceinline__ void ldsm_x2(uint32_t* r, uint32_t addr)
{
    asm volatile("ldmatrix.sync.aligned.m8n8.x2.shared.b16 {%0,%1}, [%2];"
        : "=r"(r[0]), "=r"(r[1]) : "r"(addr));
}

__device__ __forceinline__ void ldsm_x2t(uint32_t* r, uint32_t addr)
{
    asm volatile("ldmatrix.sync.aligned.m8n8.x2.trans.shared.b16 {%0,%1}, [%2];"
        : "=r"(r[0]), "=r"(r[1]) : "r"(addr));
}

__device__ __forceinline__ void mma16816h(float* c, const uint32_t* a, const uint32_t* b)
{
    asm volatile("mma.sync.aligned.m16n8k16.row.col.f32.f16.f16.f32 "
        "{%0,%1,%2,%3},{%4,%5,%6,%7},{%8,%9},{%0,%1,%2,%3};"
        : "+f"(c[0]), "+f"(c[1]), "+f"(c[2]), "+f"(c[3])
        : "r"(a[0]), "r"(a[1]), "r"(a[2]), "r"(a[3]), "r"(b[0]), "r"(b[1]));
}

__device__ __forceinline__ void cp16(uint32_t saddr, const void* g)
{
    asm volatile("cp.async.cg.shared.global [%0], [%1], 16;"
        :: "r"(saddr), "l"(g) : "memory");
}
#define CP_COMMIT() asm volatile("cp.async.commit_group;" ::: "memory")
#define CP_WAIT1()  asm volatile("cp.async.wait_group 1;" ::: "memory")
#define CP_WAIT0()  asm volatile("cp.async.wait_group 0;" ::: "memory")

// bulk async copy global -> shared with mbarrier completion
__device__ __forceinline__ void bulkcp(uint32_t dst, const void* src,
                                       uint32_t bytes, uint32_t mbar)
{
    asm volatile(
        "cp.async.bulk.shared::cluster.global.mbarrier::complete_tx::bytes "
        "[%0], [%1], %2, [%3];"
        :: "r"(dst), "l"(src), "r"(bytes), "r"(mbar) : "memory");
}

__device__ __forceinline__ void mbar_init(uint32_t a, uint32_t cnt)
{
    asm volatile("mbarrier.init.shared.b64 [%0], %1;" :: "r"(a), "r"(cnt) : "memory");
}

__device__ __forceinline__ void mbar_expect_tx(uint32_t a, uint32_t tx)
{
    asm volatile("mbarrier.arrive.expect_tx.shared.b64 _, [%0], %1;"
        :: "r"(a), "r"(tx) : "memory");
}

__device__ __forceinline__ void mbar_wait(uint32_t a, uint32_t parity)
{
    uint32_t done;
    asm volatile(
        "{\n\t.reg .pred p;\n\t"
        "mbarrier.try_wait.parity.acquire.cta.shared::cta.b64 p, [%1], %2;\n\t"
        "selp.b32 %0, 1, 0, p;\n\t}"
        : "=r"(done) : "r"(a), "r"(parity) : "memory");
    while (!done) {
        asm volatile(
            "{\n\t.reg .pred p;\n\t"
            "mbarrier.try_wait.parity.acquire.cta.shared::cta.b64 p, [%1], %2, 0x989680;\n\t"
            "selp.b32 %0, 1, 0, p;\n\t}"
            : "=r"(done) : "r"(a), "r"(parity) : "memory");
    }
}

__device__ __forceinline__ uint32_t pack2h(float a, float b)
{
    __half ha = __float2half_rn(a);
    __half hb = __float2half_rn(b);
    return (uint32_t)__half_as_ushort(ha) | ((uint32_t)__half_as_ushort(hb) << 16);
}

__device__ __forceinline__ void split2h(float a, float b, uint32_t* hi, uint32_t* lo)
{
    __half ha = __float2half_rn(a);
    __half hb = __float2half_rn(b);
    *hi = (uint32_t)__half_as_ushort(ha) | ((uint32_t)__half_as_ushort(hb) << 16);
    __half la = __float2half_rn(a - __half2float(ha));
    __half lb = __float2half_rn(b - __half2float(hb));
    *lo = (uint32_t)__half_as_ushort(la) | ((uint32_t)__half_as_ushort(lb) << 16);
}

// tiled+swizzled byte offset for element (row m in [0,M), col k in [0,768))
__device__ __forceinline__ size_t tiled_off(int m, int k)
{
    const int r  = m & 127;
    const int cb = (k & 63) * 2;
    const uint32_t sw = (uint32_t)(cb & ~15) ^ (uint32_t)((r & 7) << 4);
    return (size_t)((m >> 7) * NITC + (k >> 6)) * TILB + (size_t)(r * 128)
         + sw + (uint32_t)(cb & 15);
}

// ---------------------------------------------------------------------------
// convert fp32 -> fp16 into TILED layout. One thread = 8 consecutive k.
// ---------------------------------------------------------------------------
__global__ void cvt_f16t(const float* __restrict__ in, __half* __restrict__ out)
{
    const int idx = blockIdx.x * blockDim.x + threadIdx.x;  // over M*96
    const int m  = idx / 96;
    const int kg = idx % 96;
    const int k  = kg * 8;

    const float4 v0 = *(const float4*)(in + (size_t)m * EDIM + k);
    const float4 v1 = *(const float4*)(in + (size_t)m * EDIM + k + 4);
    uint4 o;
    o.x = pack2h(v0.x, v0.y);
    o.y = pack2h(v0.z, v0.w);
    o.z = pack2h(v1.x, v1.y);
    o.w = pack2h(v1.z, v1.w);
    *(uint4*)((char*)out + tiled_off(m, k)) = o;
}

// transpose + pack 4 weights: W[K][N] -> tiled WT (blockIdx.z selects)
__global__ void wtransT(const float* __restrict__ W0, const float* __restrict__ W1,
                        const float* __restrict__ W2, const float* __restrict__ W3,
                        __half* __restrict__ Wt)
{
    __shared__ float t[32][33];
    const int w = blockIdx.z;
    const float* W = (w == 0) ? W0 : (w == 1) ? W1 : (w == 2) ? W2 : W3;
    const int n0 = blockIdx.x * 32;
    const int k0 = blockIdx.y * 32;
    const int tx = threadIdx.x;
    const int ty = threadIdx.y;

    #pragma unroll
    for (int i = 0; i < 4; i++) {
        t[ty + 8 * i][tx] = W[(size_t)(k0 + ty + 8 * i) * EDIM + n0 + tx];
    }
    __syncthreads();
    char* base = (char*)(Wt + (size_t)w * WSZ);
    #pragma unroll
    for (int i = 0; i < 4; i++) {
        const int n = n0 + ty + 8 * i;
        const int k = k0 + tx;
        *(__half*)(base + tiled_off(n, k)) = __float2half_rn(t[tx][ty + 8 * i]);
    }
}

// ---------------------------------------------------------------------------
// Persistent fp16 single-product GEMM with BULK staging (R15-proven pipeline:
// 3 stages, full mbarrier + one __syncthreads per chunk; ring + parity run
// continuously across tile boundaries).
// variant 0 (fused QKV): ntiles=4608, t -> m=t/18, w=(t%18)/6, n=t%6.
// variant 1 (output): ntiles=1536, t -> m=t/6, n=t%6, fp32 out.
// ---------------------------------------------------------------------------
#define STGB   (2 * TILB)
#define NSTG   3
#define GEMM_SMEM (NSTG * STGB)          // 98304

__device__ __forceinline__ void gemm_prefetch(
    const char* Abase, const char* Wbase, int variant,
    int tp, int ccp, int sp, uint32_t sb, uint32_t mbF)
{
    int m, n, w;
    if (variant == 0) {
        m = tp / 18;
        const int rem = tp - m * 18;
        w = rem / 6;
        n = rem - w * 6;
    } else {
        m = tp / 6;
        n = tp - m * 6;
        w = 0;
    }
    const char* gA = Abase + ((size_t)m * NITC + ccp) * TILB;
    const char* gB = Wbase + ((size_t)w * (NITC * 6) + (size_t)n * NITC + ccp) * TILB;
    const uint32_t mb = mbF + 8 * (uint32_t)sp;
    mbar_expect_tx(mb, 2 * TILB);
    const uint32_t base = sb + (uint32_t)sp * STGB;
    bulkcp(base,        gA, TILB, mb);
    bulkcp(base + TILB, gB, TILB, mb);
}

__global__ __launch_bounds__(256, 2) void gemm_f16p(
    const __half* __restrict__ Ah, const __half* __restrict__ Wt,
    const float* __restrict__ b0, const float* __restrict__ b1,
    const float* __restrict__ b2,
    __half* __restrict__ o0, __half* __restrict__ o1, __half* __restrict__ o2,
    float* __restrict__ Cout,
    int variant, int ntiles)
{
    extern __shared__ char sm[];
    __shared__ __align__(8) unsigned long long s_mbar[NSTG];

    const int tid  = threadIdx.x;
    const int warp = tid >> 5;
    const int lane = tid & 31;
    const int wmw  = warp >> 2;
    const int wnw  = warp & 3;

    const uint32_t sb  = smem_u32(sm);
    const uint32_t mbF = smem_u32(&s_mbar[0]);

    const char* Abase = (const char*)Ah;
    const char* Wbase = (const char*)Wt;

    if (tid == 0) {
        mbar_init(mbF + 0, 1);
        mbar_init(mbF + 8, 1);
        mbar_init(mbF + 16, 1);
    }
    __syncthreads();

    const int nt = (ntiles - (int)blockIdx.x + (int)gridDim.x - 1) / (int)gridDim.x;

    if (tid == 0) {
        gemm_prefetch(Abase, Wbase, variant, (int)blockIdx.x, 0, 0, sb, mbF);
        gemm_prefetch(Abase, Wbase, variant, (int)blockIdx.x, 1, 1, sb, mbF);
    }

    const int lane15 = lane & 15;
    const int arow   = wmw * 64 + lane15;
    const uint32_t axor = (uint32_t)((arow & 7) << 4);
    const int brow   = wnw * 32 + (lane & 7) + ((lane >> 4) << 3);
    const uint32_t bxor = (uint32_t)((lane & 7) << 4);
    const uint32_t acb  = (uint32_t)((lane >> 4) * 16);
    const uint32_t bcb  = (uint32_t)(((lane >> 3) & 1) * 16);

    float acc[4][4][4];
    #pragma unroll
    for (int i = 0; i < 4; i++) {
        #pragma unroll
        for (int j = 0; j < 4; j++) {
            #pragma unroll
            for (int e = 0; e < 4; e++) {
                acc[i][j][e] = 0.0f;
            }
        }
    }

    int s    = 0;
    int par  = 0;
    int tcur = (int)blockIdx.x;

    for (int ti = 0; ti < nt; ti++) {
        for (int cc = 0; cc < NITC; cc++) {
            __syncthreads();

            if (tid == 0) {
                int ccp = cc + 2;
                int tp  = tcur;
                if (ccp >= NITC) {
                    ccp -= NITC;
                    tp  += (int)gridDim.x;
                }
                if (tp < ntiles) {
                    int sp = s + 2;
                    if (sp >= NSTG) sp -= NSTG;
                    gemm_prefetch(Abase, Wbase, variant, tp, ccp, sp, sb, mbF);
                }
            }

            mbar_wait(mbF + 8 * (uint32_t)s, (uint32_t)par);

            const uint32_t bstg = sb + (uint32_t)s * STGB;

            #pragma unroll
            for (int ks = 0; ks < 4; ks++) {
                const uint32_t kb = (uint32_t)(ks * 32);
                uint32_t ah[4][4];
                uint32_t bf[4][2];
                #pragma unroll
                for (int mf = 0; mf < 4; mf++) {
                    const uint32_t addr = bstg + (uint32_t)((arow + mf * 16) * 128) +
                                          ((acb + kb) ^ axor);
                    ldsm_x4(ah[mf], addr);
                }
                #pragma unroll
                for (int p = 0; p < 2; p++) {
                    uint32_t t4[4];
                    const uint32_t addr = bstg + TILB +
                                          (uint32_t)((brow + p * 16) * 128) +
                                          ((bcb + kb) ^ bxor);
                    ldsm_x4(t4, addr);
                    bf[2 * p][0]     = t4[0];
                    bf[2 * p][1]     = t4[1];
                    bf[2 * p + 1][0] = t4[2];
                    bf[2 * p + 1][1] = t4[3];
                }
                #pragma unroll
                for (int mf = 0; mf < 4; mf++) {
                    #pragma unroll
                    for (int nf = 0; nf < 4; nf++) {
                        mma16816h(acc[mf][nf], ah[mf], bf[nf]);
                    }
                }
            }

            s++;
            if (s >= NSTG) {
                s = 0;
                par ^= 1;
            }
        }

        // ---- epilogue for tile tcur ----
        {
            int m, n, w;
            if (variant == 0) {
                m = tcur / 18;
                const int rem = tcur - m * 18;
                w = rem / 6;
                n = rem - w * 6;
            } else {
                m = tcur / 6;
                n = tcur - m * 6;
                w = 0;
            }
            const int bm = m * 128;
            const int bn = n * 128;
            int mode;
            const float* bias;
            __half* Cf;
            if (variant == 0) {
                mode = (w == 2) ? 1 : 2;
                bias = (w == 0) ? b0 : ((w == 1) ? b1 : b2);
                Cf   = (w == 0) ? o0 : ((w == 1) ? o1 : o2);
            } else {
                mode = 0;
                bias = 0;
                Cf   = 0;
            }

            const int rbase = bm + wmw * 64 + (lane >> 2);
            const int cbase = bn + wnw * 32 + (lane & 3) * 2;
            #pragma unroll
            for (int nf = 0; nf < 4; nf++) {
                const int col = cbase + nf * 8;
                float bb0 = 0.0f;
                float bb1 = 0.0f;
                if (bias != 0) {
                    bb0 = bias[col];
                    bb1 = bias[col + 1];
                }
                const int hd = col & 63;
                const int pr = hd >> 1;
                const int jf = pr & 15;
                const float invf = __expf(-0.57564627324851142f * (float)jf);

                #pragma unroll
                for (int mf = 0; mf < 4; mf++) {
                    const int row = rbase + mf * 16;
                    float a0 = acc[mf][nf][0] + bb0;
                    float a1 = acc[mf][nf][1] + bb1;
                    float a2 = acc[mf][nf][2] + bb0;
                    float a3 = acc[mf][nf][3] + bb1;

                    if (mode == 2) {
                        const int p0 = row & 255;
                        const int p8 = (row + 8) & 255;
                        const float pos0 = (pr < 16) ? (float)(p0 & 15) : (float)(p0 >> 4);
                        const float pos8 = (pr < 16) ? (float)(p8 & 15) : (float)(p8 >> 4);
                        float s0, c0, s8, c8;
                        sincosf(pos0 * invf, &s0, &c0);
                        sincosf(pos8 * invf, &s8, &c8);
                        const float r0 = a0 * c0 - a1 * s0;
                        const float r1 = a1 * c0 + a0 * s0;
                        const float r2 = a2 * c8 - a3 * s8;
                        const float r3 = a3 * c8 + a2 * s8;
                        a0 = r0; a1 = r1; a2 = r2; a3 = r3;
                    }

                    if (mode >= 1) {
                        *(uint32_t*)(Cf + (size_t)row * EDIM + col)       = pack2h(a0, a1);
                        *(uint32_t*)(Cf + (size_t)(row + 8) * EDIM + col) = pack2h(a2, a3);
                    } else {
                        float2 v0;
                        float2 v1;
                        v0.x = a0; v0.y = a1;
                        v1.x = a2; v1.y = a3;
                        *(float2*)(Cout + (size_t)row * EDIM + col)       = v0;
                        *(float2*)(Cout + (size_t)(row + 8) * EDIM + col) = v1;
                    }
                }
            }

            #pragma unroll
            for (int i = 0; i < 4; i++) {
                #pragma unroll
                for (int j = 0; j < 4; j++) {
                    #pragma unroll
                    for (int e = 0; e < 4; e++) {
                        acc[i][j][e] = 0.0f;
                    }
                }
            }
        }

        tcur += (int)gridDim.x;
    }
}

// ---------------------------------------------------------------------------
// Tensor-core attention, all-fp16 (Q,K,V single fp16; P fp16 hi/lo).
// Writes y as fp16 in TILED layout for the output GEMM. (Unchanged from R15.)
// ---------------------------------------------------------------------------
#define SROWB   144
#define ATILEB  (64 * SROWB)
#define ASTGB   (2 * ATILEB)
#define ATTN_SMEM (2 * ASTGB)            // 36864

__global__ __launch_bounds__(256, 2) void attn_mma(
    const __half* __restrict__ qf, const __half* __restrict__ kf2,
    const __half* __restrict__ vf, __half* __restrict__ yh)
{
    extern __shared__ char sm[];

    const int tid   = threadIdx.x;
    const int warp  = tid >> 5;
    const int lane  = tid & 31;
    const int l4    = lane >> 2;
    const int l2    = (lane & 3) * 2;
    const int lane15 = lane & 15;

    const int bt   = blockIdx.x;
    const int h    = blockIdx.y >> 1;
    const int half = blockIdx.y & 1;

    const int qrow0 = bt * 256 + half * 128 + warp * 16;
    const uint32_t sb = smem_u32(sm);

    uint32_t qh[4][4];
    {
        const size_t qb = (size_t)(qrow0 + l4) * EDIM + h * 64;
        #pragma unroll
        for (int kfi = 0; kfi < 4; kfi++) {
            const int c = kfi * 16 + l2;
            qh[kfi][0] = *(const uint32_t*)(qf + qb + c);
            qh[kfi][1] = *(const uint32_t*)(qf + qb + (size_t)8 * EDIM + c);
            qh[kfi][2] = *(const uint32_t*)(qf + qb + c + 8);
            qh[kfi][3] = *(const uint32_t*)(qf + qb + (size_t)8 * EDIM + c + 8);
        }
    }

    float O[8][4];
    #pragma unroll
    for (int nf = 0; nf < 8; nf++) {
        #pragma unroll
        for (int e = 0; e < 4; e++) {
            O[nf][e] = 0.0f;
        }
    }
    float sum0 = 0.0f;
    float sum1 = 0.0f;

    const int lrow0 = tid >> 3;
    const int lseg0 = tid & 7;
    const int lrow1 = (tid + 256) >> 3;

    #define ATTN_LOAD(c, s) do {                                                   \
        const int jg0 = bt * 256 + (c) * 64;                                        \
        const uint32_t base = sb + (uint32_t)(s) * ASTGB;                           \
        size_t g0 = (size_t)(jg0 + lrow0) * EDIM + h * 64 + lseg0 * 8;              \
        uint32_t d0 = base + (uint32_t)(lrow0 * SROWB + lseg0 * 16);                \
        cp16(d0,          kf2 + g0);                                                \
        cp16(d0 + ATILEB, vf + g0);                                                 \
        size_t g1 = (size_t)(jg0 + lrow1) * EDIM + h * 64 + lseg0 * 8;              \
        uint32_t d1 = base + (uint32_t)(lrow1 * SROWB + lseg0 * 16);                \
        cp16(d1,          kf2 + g1);                                                \
        cp16(d1 + ATILEB, vf + g1);                                                 \
        CP_COMMIT();                                                                \
    } while (0)

    ATTN_LOAD(0, 0);

    const uint32_t bqoff = (uint32_t)((lane15 & 7) * SROWB + ((lane15 >> 3) & 1) * 16);
    const uint32_t bvoff = (uint32_t)(lane15 * SROWB);

    for (int c = 0; c < 4; c++) {
        const int s = c & 1;
        if (c < 3) {
            ATTN_LOAD(c + 1, s ^ 1);
            CP_WAIT1();
        } else {
            CP_WAIT0();
        }
        __syncthreads();

        const uint32_t kb = sb + (uint32_t)s * ASTGB;

        float S[8][4];
        #pragma unroll
        for (int nf = 0; nf < 8; nf++) {
            #pragma unroll
            for (int e = 0; e < 4; e++) {
                S[nf][e] = 0.0f;
            }
        }
        #pragma unroll
        for (int nf = 0; nf < 8; nf++) {
            uint32_t bh[4][2];
            #pragma unroll
            for (int kfi = 0; kfi < 4; kfi++) {
                const uint32_t a = kb + (uint32_t)(nf * 8 * SROWB + kfi * 32) + bqoff;
                ldsm_x2(bh[kfi], a);
            }
            #pragma unroll
            for (int kfi = 0; kfi < 4; kfi++) {
                mma16816h(S[nf], qh[kfi], bh[kfi]);
            }
        }

        uint32_t ph[4][4];
        uint32_t pl[4][4];
        #pragma unroll
        for (int nf = 0; nf < 8; nf++) {
            float p0 = __expf(S[nf][0] * 0.125f);
            float p1 = __expf(S[nf][1] * 0.125f);
            float p2 = __expf(S[nf][2] * 0.125f);
            float p3 = __expf(S[nf][3] * 0.125f);
            sum0 += p0 + p1;
            sum1 += p2 + p3;
            const int kf2i = nf >> 1;
            const int o    = (nf & 1) * 2;
            split2h(p0, p1, &ph[kf2i][o],     &pl[kf2i][o]);
            split2h(p2, p3, &ph[kf2i][o + 1], &pl[kf2i][o + 1]);
        }

        #pragma unroll
        for (int nf = 0; nf < 8; nf++) {
            #pragma unroll
            for (int kfi = 0; kfi < 4; kfi++) {
                uint32_t vh2[2];
                const uint32_t a = kb + ATILEB +
                                   (uint32_t)(kfi * 16 * SROWB + nf * 16) + bvoff;
                ldsm_x2t(vh2, a);
                mma16816h(O[nf], ph[kfi], vh2);
                mma16816h(O[nf], pl[kfi], vh2);
            }
        }
        __syncthreads();
    }

    sum0 += __shfl_xor_sync(0xffffffffu, sum0, 1);
    sum0 += __shfl_xor_sync(0xffffffffu, sum0, 2);
    sum1 += __shfl_xor_sync(0xffffffffu, sum1, 1);
    sum1 += __shfl_xor_sync(0xffffffffu, sum1, 2);
    const float inv0 = 1.0f / sum0;
    const float inv1 = 1.0f / sum1;

    const int r0g = qrow0 + l4;
    const int r1g = r0g + 8;
    char* yb = (char*)yh;
    #pragma unroll
    for (int nf = 0; nf < 8; nf++) {
        const uint32_t grp = (uint32_t)(nf * 16) ^ (uint32_t)((l4 & 7) << 4);
        const uint32_t within = (uint32_t)((lane & 3) * 4);
        const size_t o0 = (size_t)((r0g >> 7) * NITC + h) * TILB +
                          (size_t)((r0g & 127) * 128) + grp + within;
        const size_t o1 = (size_t)((r1g >> 7) * NITC + h) * TILB +
                          (size_t)((r1g & 127) * 128) + grp + within;
        *(uint32_t*)(yb + o0) = pack2h(O[nf][0] * inv0, O[nf][1] * inv0);
        *(uint32_t*)(yb + o1) = pack2h(O[nf][2] * inv1, O[nf][3] * inv1);
    }
}

// ---------------------------------------------------------------------------
extern "C" void kernel_launch(void* const* d_in, const int* in_sizes, int n_in,
                              void* d_out, int out_size)
{
    const float* x  = (const float*)d_in[0];
    const float* Wq = (const float*)d_in[1];
    const float* bq = (const float*)d_in[2];
    const float* Wk = (const float*)d_in[3];
    const float* bk = (const float*)d_in[4];
    const float* Wv = (const float*)d_in[5];
    const float* bv = (const float*)d_in[6];
    const float* Wo = (const float*)d_in[7];
    float* out = (float*)d_out;

    __half *xh = 0, *yh = 0, *wt = 0, *qf = 0, *kf = 0, *vf = 0;
    cudaGetSymbolAddress((void**)&xh, g_xh);
    cudaGetSymbolAddress((void**)&yh, g_yh);
    cudaGetSymbolAddress((void**)&wt, g_wt);
    cudaGetSymbolAddress((void**)&qf, g_qf);
    cudaGetSymbolAddress((void**)&kf, g_kf);
    cudaGetSymbolAddress((void**)&vf, g_vf);

    cudaFuncSetAttribute(gemm_f16p, cudaFuncAttributeMaxDynamicSharedMemorySize, GEMM_SMEM);
    cudaFuncSetAttribute(attn_mma, cudaFuncAttributeMaxDynamicSharedMemorySize, ATTN_SMEM);

    cvt_f16t<<<(M_ROWS * 96) / 256, 256>>>(x, xh);
    wtransT<<<dim3(EDIM / 32, EDIM / 32, 4), dim3(32, 8)>>>(Wq, Wk, Wv, Wo, wt);

    // fused persistent QKV: 4608 tiles
    gemm_f16p<<<PGRID, 256, GEMM_SMEM>>>(xh, wt, bq, bk, bv, qf, kf, vf,
                                         (float*)0, 0, 4608);

    attn_mma<<<dim3(128, NHEAD * 2), 256, ATTN_SMEM>>>(qf, kf, vf, yh);

    // persistent output GEMM: 1536 tiles
    gemm_f16p<<<PGRID, 256, GEMM_SMEM>>>(yh, wt + 3 * WSZ,
                                         (const float*)0, (const float*)0, (const float*)0,
                                         (__half*)0, (__half*)0, (__half*)0,
                                         out, 1, 1536);
}